// round 8
// baseline (speedup 1.0000x reference)
#include <cuda_runtime.h>
#include <cuda_fp16.h>
#include <math.h>
#include <stdint.h>

#define S_  64
#define B_  64
#define K_  512
#define H_  512
#define E_  512
#define A_  512
#define V_  32000
#define G3H 1536

// ---------------- scratch (static device memory; no allocations) ----------------
__device__ float g_keys[S_ * B_ * A_];
__device__ float g_h[B_ * H_];
__device__ float g_logits[(size_t)B_ * V_];
__device__ float g_partA[16 * B_ * G3H];
__device__ float g_partB[16 * B_ * G3H];
__device__ int   g_tok[B_];
// fp16 split weights
__device__ __half g_W2T_hi[(size_t)V_ * 512];     // [n][k]
__device__ __half g_W2T_lo[(size_t)V_ * 512];     // [n][k] (x1024)
__device__ __half g_Wih_hi[G3H * 1024];           // [n][k] (native layout)
__device__ __half g_Wih_lo[G3H * 1024];
__device__ __half g_Whh_hi[G3H * 512];
__device__ __half g_Whh_lo[G3H * 512];
__device__ __half g_W1T_hi[512 * 1536];           // [n][k]
__device__ __half g_W1T_lo[512 * 1536];
__device__ __half g_WqT_hi[512 * 512];
__device__ __half g_WqT_lo[512 * 512];
// fp16 split activations: rows 0-63 hi, rows 64-127 lo*1024
__device__ __half g_hid16[128 * 512];
__device__ __half g_h16[128 * 512];
__device__ __half g_rnn16[128 * 1024];            // [x_emb | ctx]
__device__ __half g_mlp16[128 * 1536];            // [x_emb | h | ctx]

// ---------------- fast math ----------------
__device__ __forceinline__ float ftanh(float x) {
    float t = __expf(-2.f * fabsf(x));
    float r = __fdividef(1.f - t, 1.f + t);
    return copysignf(r, x);
}
__device__ __forceinline__ float fsigmoid(float x) {
    return __fdividef(1.f, 1.f + __expf(-x));
}

// ---------------- packed f32x2 FMA ----------------
__device__ __forceinline__ float2 ffma2(float2 a, float2 b, float2 c) {
    unsigned long long ua = *reinterpret_cast<unsigned long long*>(&a);
    unsigned long long ub = *reinterpret_cast<unsigned long long*>(&b);
    unsigned long long uc = *reinterpret_cast<unsigned long long*>(&c);
    unsigned long long ud;
    asm("fma.rn.f32x2 %0, %1, %2, %3;" : "=l"(ud) : "l"(ua), "l"(ub), "l"(uc));
    return *reinterpret_cast<float2*>(&ud);
}

// ---------------- baseline-PTX async helpers ----------------
__device__ __forceinline__ uint32_t smem_to_u32(const void* p) {
    uint32_t a;
    asm("{ .reg .u64 t; cvta.to.shared.u64 t, %1; cvt.u32.u64 %0, t; }"
        : "=r"(a) : "l"(p));
    return a;
}
#define MBAR_INIT(mb, c) asm volatile("mbarrier.init.shared.b64 [%0], %1;" :: "r"(mb), "r"((uint32_t)(c)) : "memory")
#define MBAR_ARRIVE_TX(mb, tx) asm volatile("mbarrier.arrive.expect_tx.shared.b64 _, [%0], %1;" :: "r"(mb), "r"((uint32_t)(tx)) : "memory")
#define MBAR_WAIT(mb, par) do {                                              \
    uint32_t _m = (mb), _p = (par), _d;                                      \
    asm volatile("{\n\t.reg .pred p;\n\t"                                    \
        "mbarrier.try_wait.parity.acquire.cta.shared::cta.b64 p, [%1], %2;\n\t" \
        "selp.b32 %0, 1, 0, p;\n\t}" : "=r"(_d) : "r"(_m), "r"(_p) : "memory"); \
    if (!_d) {                                                               \
        asm volatile("{\n\t.reg .pred P1;\n\tWL_%=:\n\t"                     \
            "mbarrier.try_wait.parity.acquire.cta.shared::cta.b64 P1, [%0], %1, 0x989680;\n\t" \
            "@P1 bra.uni WD_%=;\n\tbra.uni WL_%=;\n\tWD_%=:\n\t}"            \
            :: "r"(_m), "r"(_p) : "memory");                                 \
    }                                                                        \
} while (0)

__device__ __forceinline__ void bulk128(uint32_t dst, const void* src, uint32_t mbar) {
    asm volatile(
        "cp.async.bulk.shared::cluster.global.mbarrier::complete_tx::bytes "
        "[%0], [%1], %2, [%3];"
        :: "r"(dst), "l"(src), "r"(128u), "r"(mbar) : "memory");
}
__device__ __forceinline__ void ldsm4(uint32_t& r0, uint32_t& r1, uint32_t& r2,
                                      uint32_t& r3, uint32_t sa) {
    asm volatile("ldmatrix.sync.aligned.m8n8.x4.shared.b16 {%0,%1,%2,%3}, [%4];"
                 : "=r"(r0), "=r"(r1), "=r"(r2), "=r"(r3) : "r"(sa));
}
__device__ __forceinline__ void mma16816(float* c, uint32_t a0, uint32_t a1,
                                         uint32_t a2, uint32_t a3,
                                         uint32_t b0, uint32_t b1) {
    asm volatile(
        "mma.sync.aligned.m16n8k16.row.col.f32.f16.f16.f32 "
        "{%0,%1,%2,%3}, {%4,%5,%6,%7}, {%8,%9}, {%0,%1,%2,%3};"
        : "+f"(c[0]), "+f"(c[1]), "+f"(c[2]), "+f"(c[3])
        : "r"(a0), "r"(a1), "r"(a2), "r"(a3), "r"(b0), "r"(b1));
}

// shared HMMA inner loop: one 64-half K chunk (4 x k16), rows at 144B pitch
template<int NT>
__device__ __forceinline__ void lg_chunk_compute(
    uint32_t ab, uint32_t bb, int warpM, int warpN, int lane,
    float (&acc)[2][NT][4])
{
#pragma unroll
    for (int kk = 0; kk < 4; kk++) {
        uint32_t af[2][4];
#pragma unroll
        for (int mt = 0; mt < 2; mt++) {
            int row = warpM + mt * 16 + (lane & 15);
            uint32_t sa = ab + row * 144 + kk * 32 + ((lane >> 4) << 4);
            ldsm4(af[mt][0], af[mt][1], af[mt][2], af[mt][3], sa);
        }
#pragma unroll
        for (int np = 0; np < NT / 2; np++) {
            int nr = warpN + np * 16 + (lane & 7) + (((lane >> 4) & 1) << 3);
            uint32_t sbad = bb + nr * 144 + kk * 32 + (((lane >> 3) & 1) << 4);
            uint32_t b0, b1, b2r, b3;
            ldsm4(b0, b1, b2r, b3, sbad);
            mma16816(acc[0][2 * np],     af[0][0], af[0][1], af[0][2], af[0][3], b0, b1);
            mma16816(acc[1][2 * np],     af[1][0], af[1][1], af[1][2], af[1][3], b0, b1);
            mma16816(acc[0][2 * np + 1], af[0][0], af[0][1], af[0][2], af[0][3], b2r, b3);
            mma16816(acc[1][2 * np + 1], af[1][0], af[1][1], af[1][2], af[1][3], b2r, b3);
        }
    }
}

// ============ generic HMMA fp16-split small GEMM ============
// Cpart[z][64][N] = A[64,K] @ W[K,N] split-K partial (hh + (lh+hl)/1024), no bias.
// A16: stacked [hi; lo*1024] (128 x K). W hi/lo: [n][k]. grid (N/128, splitZ).
#define HS_AOFF(b) ((b) * 18432)
#define HS_BOFF(b) (36864 + (b) * 18432)
#define HS_POFF    73728
#define HS_PSTR    132
#define HS_BAR0    107520
#define HS_BAR1    107528
#define HS_SMEM    107552

template<int NC>
__global__ void __launch_bounds__(256, 1)
hmma_small(const __half* __restrict__ A16, const __half* __restrict__ Whi,
           const __half* __restrict__ Wlo, float* __restrict__ Cpart,
           int K, int N)
{
    extern __shared__ __align__(16) char sm[];
    const uint32_t sb = smem_to_u32(sm);
    const int tid = threadIdx.x;
    const int w = tid >> 5, lane = tid & 31;
    const int n_base = blockIdx.x * 128;
    const int k_base = blockIdx.y * (NC * 64);
    float* P = (float*)(sm + HS_POFF);
    const float IS = 0.0009765625f;
    const int g = lane >> 2, tq = lane & 3;

    if (tid == 0) { MBAR_INIT(sb + HS_BAR0, 256); MBAR_INIT(sb + HS_BAR1, 256); }
    __syncthreads();
    int ph0 = 0, ph1 = 0;

    // ---- pass 1: A stacked (M=128) x Whi ----
    {
        const int wm = w >> 1;
        const int warpM = wm * 32, warpN = (w & 1) * 64;
        float acc[2][8][4];
#pragma unroll
        for (int i = 0; i < 2; i++)
#pragma unroll
            for (int j = 0; j < 8; j++)
#pragma unroll
                for (int q = 0; q < 4; q++) acc[i][j][q] = 0.f;

        {
            uint32_t bar = sb + HS_BAR0;
            MBAR_ARRIVE_TX(bar, 128u);
            if (tid < 128)
                bulk128(sb + HS_AOFF(0) + tid * 144,
                        A16 + (size_t)tid * K + k_base, bar);
            else
                bulk128(sb + HS_BOFF(0) + (tid - 128) * 144,
                        Whi + (size_t)(n_base + tid - 128) * K + k_base, bar);
        }
        for (int c = 0; c < NC; c++) {
            const int buf = c & 1;
            if (c + 1 < NC) {
                uint32_t bar = sb + ((buf ^ 1) ? HS_BAR1 : HS_BAR0);
                MBAR_ARRIVE_TX(bar, 128u);
                if (tid < 128)
                    bulk128(sb + HS_AOFF(buf ^ 1) + tid * 144,
                            A16 + (size_t)tid * K + k_base + (c + 1) * 64, bar);
                else
                    bulk128(sb + HS_BOFF(buf ^ 1) + (tid - 128) * 144,
                            Whi + (size_t)(n_base + tid - 128) * K + k_base + (c + 1) * 64, bar);
            }
            if (buf == 0) { MBAR_WAIT(sb + HS_BAR0, ph0); ph0 ^= 1; }
            else          { MBAR_WAIT(sb + HS_BAR1, ph1); ph1 ^= 1; }
            __syncthreads();
            lg_chunk_compute<8>(sb + HS_AOFF(buf), sb + HS_BOFF(buf),
                                warpM, warpN, lane, acc);
            __syncthreads();
        }
        if (wm >= 2) {
#pragma unroll
            for (int mt = 0; mt < 2; mt++) {
                int m = warpM - 64 + mt * 16 + g;
#pragma unroll
                for (int nt = 0; nt < 8; nt++) {
                    int col = warpN + nt * 8 + tq * 2;
                    P[m * HS_PSTR + col]           = acc[mt][nt][0] * IS;
                    P[m * HS_PSTR + col + 1]       = acc[mt][nt][1] * IS;
                    P[(m + 8) * HS_PSTR + col]     = acc[mt][nt][2] * IS;
                    P[(m + 8) * HS_PSTR + col + 1] = acc[mt][nt][3] * IS;
                }
            }
        }
        __syncthreads();
        if (wm < 2) {
#pragma unroll
            for (int mt = 0; mt < 2; mt++) {
                int m = warpM + mt * 16 + g;
#pragma unroll
                for (int nt = 0; nt < 8; nt++) {
                    int col = warpN + nt * 8 + tq * 2;
                    P[m * HS_PSTR + col]           += acc[mt][nt][0];
                    P[m * HS_PSTR + col + 1]       += acc[mt][nt][1];
                    P[(m + 8) * HS_PSTR + col]     += acc[mt][nt][2];
                    P[(m + 8) * HS_PSTR + col + 1] += acc[mt][nt][3];
                }
            }
        }
        __syncthreads();
    }

    // ---- pass 2: A hi (M=64) x Wlo ----
    {
        const int warpM = (w >> 2) * 32, warpN = (w & 3) * 32;
        float acc[2][4][4];
#pragma unroll
        for (int i = 0; i < 2; i++)
#pragma unroll
            for (int j = 0; j < 4; j++)
#pragma unroll
                for (int q = 0; q < 4; q++) acc[i][j][q] = 0.f;

        {
            uint32_t bar = sb + HS_BAR0;
            uint32_t tx = (tid < 64 || tid >= 128) ? 128u : 0u;
            MBAR_ARRIVE_TX(bar, tx);
            if (tid < 64)
                bulk128(sb + HS_AOFF(0) + tid * 144,
                        A16 + (size_t)tid * K + k_base, bar);
            else if (tid >= 128)
                bulk128(sb + HS_BOFF(0) + (tid - 128) * 144,
                        Wlo + (size_t)(n_base + tid - 128) * K + k_base, bar);
        }
        for (int c = 0; c < NC; c++) {
            const int buf = c & 1;
            if (c + 1 < NC) {
                uint32_t bar = sb + ((buf ^ 1) ? HS_BAR1 : HS_BAR0);
                uint32_t tx = (tid < 64 || tid >= 128) ? 128u : 0u;
                MBAR_ARRIVE_TX(bar, tx);
                if (tid < 64)
                    bulk128(sb + HS_AOFF(buf ^ 1) + tid * 144,
                            A16 + (size_t)tid * K + k_base + (c + 1) * 64, bar);
                else if (tid >= 128)
                    bulk128(sb + HS_BOFF(buf ^ 1) + (tid - 128) * 144,
                            Wlo + (size_t)(n_base + tid - 128) * K + k_base + (c + 1) * 64, bar);
            }
            if (buf == 0) { MBAR_WAIT(sb + HS_BAR0, ph0); ph0 ^= 1; }
            else          { MBAR_WAIT(sb + HS_BAR1, ph1); ph1 ^= 1; }
            __syncthreads();
            lg_chunk_compute<4>(sb + HS_AOFF(buf), sb + HS_BOFF(buf),
                                warpM, warpN, lane, acc);
            __syncthreads();
        }
#pragma unroll
        for (int mt = 0; mt < 2; mt++) {
            int m = warpM + mt * 16 + g;
#pragma unroll
            for (int nt = 0; nt < 4; nt++) {
                int col = warpN + nt * 8 + tq * 2;
                P[m * HS_PSTR + col]           += acc[mt][nt][0] * IS;
                P[m * HS_PSTR + col + 1]       += acc[mt][nt][1] * IS;
                P[(m + 8) * HS_PSTR + col]     += acc[mt][nt][2] * IS;
                P[(m + 8) * HS_PSTR + col + 1] += acc[mt][nt][3] * IS;
            }
        }
        __syncthreads();
    }

    // write split-K partial
    for (int i = tid; i < 2048; i += 256) {
        int m = i >> 5;
        int c4 = (i & 31) * 4;
        float4 p = *(float4*)&P[m * HS_PSTR + c4];
        *(float4*)&Cpart[(size_t)blockIdx.y * 64 * N + (size_t)m * N + n_base + c4] = p;
    }
}

// ============ merged HMMA fp16-split logits GEMM (unchanged, passing) ============
#define LG2_AOFF(b) ((b) * 18432)
#define LG2_BOFF(b) (36864 + (b) * 36864)
#define LG2_POFF    110592
#define LG2_PSTR    264
#define LG2_BAR0    178176
#define LG2_BAR1    178184
#define LG2_SMEM    178208

__global__ void __launch_bounds__(256, 1)
logits_fused(const float* __restrict__ b2)
{
    extern __shared__ __align__(16) char sm[];
    const uint32_t sb = smem_to_u32(sm);
    const int tid = threadIdx.x;
    const int w = tid >> 5, lane = tid & 31;
    const int n_base = blockIdx.x * 256;
    float* P = (float*)(sm + LG2_POFF);
    const float IS = 0.0009765625f;
    const int g = lane >> 2, tq = lane & 3;

    if (tid == 0) { MBAR_INIT(sb + LG2_BAR0, 256); MBAR_INIT(sb + LG2_BAR1, 256); }
    __syncthreads();
    int ph0 = 0, ph1 = 0;

    // pass 1: [hid_hi; hid_lo*1024] (M=128) x W2T_hi
    {
        const int wm = w >> 1;
        const int warpM = wm * 32, warpN = (w & 1) * 128;
        float acc[2][16][4];
#pragma unroll
        for (int i = 0; i < 2; i++)
#pragma unroll
            for (int j = 0; j < 16; j++)
#pragma unroll
                for (int q = 0; q < 4; q++) acc[i][j][q] = 0.f;

        {
            uint32_t bar = sb + LG2_BAR0;
            int myA = (tid < 128) ? 1 : 0;
            MBAR_ARRIVE_TX(bar, 128u * (1 + myA));
            bulk128(sb + LG2_BOFF(0) + tid * 144,
                    g_W2T_hi + (size_t)(n_base + tid) * 512, bar);
            if (myA)
                bulk128(sb + LG2_AOFF(0) + tid * 144, g_hid16 + tid * 512, bar);
        }
        for (int c = 0; c < 8; c++) {
            const int buf = c & 1;
            if (c + 1 < 8) {
                uint32_t bar = sb + ((buf ^ 1) ? LG2_BAR1 : LG2_BAR0);
                int myA = (tid < 128) ? 1 : 0;
                MBAR_ARRIVE_TX(bar, 128u * (1 + myA));
                bulk128(sb + LG2_BOFF(buf ^ 1) + tid * 144,
                        g_W2T_hi + (size_t)(n_base + tid) * 512 + (c + 1) * 64, bar);
                if (myA)
                    bulk128(sb + LG2_AOFF(buf ^ 1) + tid * 144,
                            g_hid16 + tid * 512 + (c + 1) * 64, bar);
            }
            if (buf == 0) { MBAR_WAIT(sb + LG2_BAR0, ph0); ph0 ^= 1; }
            else          { MBAR_WAIT(sb + LG2_BAR1, ph1); ph1 ^= 1; }
            __syncthreads();
            lg_chunk_compute<16>(sb + LG2_AOFF(buf), sb + LG2_BOFF(buf),
                                 warpM, warpN, lane, acc);
            __syncthreads();
        }
        if (wm >= 2) {
#pragma unroll
            for (int mt = 0; mt < 2; mt++) {
                int m = warpM - 64 + mt * 16 + g;
#pragma unroll
                for (int nt = 0; nt < 16; nt++) {
                    int col = warpN + nt * 8 + tq * 2;
                    P[m * LG2_PSTR + col]           = acc[mt][nt][0] * IS;
                    P[m * LG2_PSTR + col + 1]       = acc[mt][nt][1] * IS;
                    P[(m + 8) * LG2_PSTR + col]     = acc[mt][nt][2] * IS;
                    P[(m + 8) * LG2_PSTR + col + 1] = acc[mt][nt][3] * IS;
                }
            }
        }
        __syncthreads();
        if (wm < 2) {
#pragma unroll
            for (int mt = 0; mt < 2; mt++) {
                int m = warpM + mt * 16 + g;
#pragma unroll
                for (int nt = 0; nt < 16; nt++) {
                    int col = warpN + nt * 8 + tq * 2;
                    P[m * LG2_PSTR + col]           += acc[mt][nt][0];
                    P[m * LG2_PSTR + col + 1]       += acc[mt][nt][1];
                    P[(m + 8) * LG2_PSTR + col]     += acc[mt][nt][2];
                    P[(m + 8) * LG2_PSTR + col + 1] += acc[mt][nt][3];
                }
            }
        }
        __syncthreads();
    }

    // pass 2: hid_hi (M=64) x W2T_lo*1024
    {
        const int warpM = (w >> 2) * 32, warpN = (w & 3) * 64;
        float acc[2][8][4];
#pragma unroll
        for (int i = 0; i < 2; i++)
#pragma unroll
            for (int j = 0; j < 8; j++)
#pragma unroll
                for (int q = 0; q < 4; q++) acc[i][j][q] = 0.f;

        {
            uint32_t bar = sb + LG2_BAR0;
            int myA = (tid < 64) ? 1 : 0;
            MBAR_ARRIVE_TX(bar, 128u * (1 + myA));
            bulk128(sb + LG2_BOFF(0) + tid * 144,
                    g_W2T_lo + (size_t)(n_base + tid) * 512, bar);
            if (myA)
                bulk128(sb + LG2_AOFF(0) + tid * 144, g_hid16 + tid * 512, bar);
        }
        for (int c = 0; c < 8; c++) {
            const int buf = c & 1;
            if (c + 1 < 8) {
                uint32_t bar = sb + ((buf ^ 1) ? LG2_BAR1 : LG2_BAR0);
                int myA = (tid < 64) ? 1 : 0;
                MBAR_ARRIVE_TX(bar, 128u * (1 + myA));
                bulk128(sb + LG2_BOFF(buf ^ 1) + tid * 144,
                        g_W2T_lo + (size_t)(n_base + tid) * 512 + (c + 1) * 64, bar);
                if (myA)
                    bulk128(sb + LG2_AOFF(buf ^ 1) + tid * 144,
                            g_hid16 + tid * 512 + (c + 1) * 64, bar);
            }
            if (buf == 0) { MBAR_WAIT(sb + LG2_BAR0, ph0); ph0 ^= 1; }
            else          { MBAR_WAIT(sb + LG2_BAR1, ph1); ph1 ^= 1; }
            __syncthreads();
            lg_chunk_compute<8>(sb + LG2_AOFF(buf), sb + LG2_BOFF(buf),
                                warpM, warpN, lane, acc);
            __syncthreads();
        }
#pragma unroll
        for (int mt = 0; mt < 2; mt++) {
            int m = warpM + mt * 16 + g;
#pragma unroll
            for (int nt = 0; nt < 8; nt++) {
                int col = warpN + nt * 8 + tq * 2;
                P[m * LG2_PSTR + col]           += acc[mt][nt][0] * IS;
                P[m * LG2_PSTR + col + 1]       += acc[mt][nt][1] * IS;
                P[(m + 8) * LG2_PSTR + col]     += acc[mt][nt][2] * IS;
                P[(m + 8) * LG2_PSTR + col + 1] += acc[mt][nt][3] * IS;
            }
        }
        __syncthreads();
    }

    for (int i = tid; i < 64 * 64; i += 256) {
        int m = i >> 6;
        int c4 = (i & 63) * 4;
        float4 p = *(float4*)&P[m * LG2_PSTR + c4];
        float4 bb = *(const float4*)&b2[n_base + c4];
        p.x += bb.x; p.y += bb.y; p.z += bb.z; p.w += bb.w;
        *(float4*)&g_logits[(size_t)m * V_ + n_base + c4] = p;
    }
}

// ============ fp32 GEMM (keys projection only) ============
__device__ __forceinline__ void gemm_compute(
    const float (*As2)[130], const float (*Bs)[128],
    int m0, int bn, float2 acc[4][4])
{
#pragma unroll
    for (int kk = 0; kk < 16; kk++) {
        float2 ad[4];
#pragma unroll
        for (int i = 0; i < 4; i++)
            ad[i] = *(const float2*)&As2[kk][2 * (m0 + i)];
        float4 b0 = *(const float4*)&Bs[kk][bn];
        float4 b1 = *(const float4*)&Bs[kk][bn + 64];
        float2 bp[4];
        bp[0] = make_float2(b0.x, b0.y); bp[1] = make_float2(b0.z, b0.w);
        bp[2] = make_float2(b1.x, b1.y); bp[3] = make_float2(b1.z, b1.w);
#pragma unroll
        for (int i = 0; i < 4; i++)
#pragma unroll
            for (int j = 0; j < 4; j++)
                acc[i][j] = ffma2(ad[i], bp[j], acc[i][j]);
    }
}

__global__ void __launch_bounds__(256, 3)
gemm64(const float* __restrict__ A, const float* __restrict__ B,
       float* __restrict__ C, int K, int N)
{
    __shared__ __align__(16) float As2[2][16][130];
    __shared__ __align__(16) float Bs[2][16][128];

    const int tid = threadIdx.x;
    const int m_base = blockIdx.y * 64;
    const int n_base = blockIdx.x * 128;

    const int ty = tid >> 4, tx = tid & 15;
    const int m0 = ty * 4;
    const int bn = tx * 4;
    const int am = tid >> 2, ak = (tid & 3) * 4;
    const int bk0 = tid >> 4;

    const float* Aload = A + (size_t)(m_base + am) * K + ak;
    const float* Bload = B + (size_t)bk0 * N + n_base + bn;

    float2 acc[4][4];
#pragma unroll
    for (int i = 0; i < 4; i++)
#pragma unroll
        for (int j = 0; j < 4; j++) acc[i][j] = make_float2(0.f, 0.f);

    float4 aR  = *(const float4*)Aload;
    float4 bR0 = *(const float4*)Bload;
    float4 bR1 = *(const float4*)(Bload + 64);

    *(float2*)&As2[0][ak + 0][2 * am] = make_float2(aR.x, aR.x);
    *(float2*)&As2[0][ak + 1][2 * am] = make_float2(aR.y, aR.y);
    *(float2*)&As2[0][ak + 2][2 * am] = make_float2(aR.z, aR.z);
    *(float2*)&As2[0][ak + 3][2 * am] = make_float2(aR.w, aR.w);
    *(float4*)&Bs[0][bk0][bn]      = bR0;
    *(float4*)&Bs[0][bk0][bn + 64] = bR1;
    __syncthreads();

    int buf = 0;
    for (int k0 = 16; k0 < K; k0 += 16) {
        float4 aN  = *(const float4*)(Aload + k0);
        float4 bN0 = *(const float4*)(Bload + (size_t)k0 * N);
        float4 bN1 = *(const float4*)(Bload + (size_t)k0 * N + 64);

        gemm_compute(As2[buf], Bs[buf], m0, bn, acc);

        int nb = buf ^ 1;
        *(float2*)&As2[nb][ak + 0][2 * am] = make_float2(aN.x, aN.x);
        *(float2*)&As2[nb][ak + 1][2 * am] = make_float2(aN.y, aN.y);
        *(float2*)&As2[nb][ak + 2][2 * am] = make_float2(aN.z, aN.z);
        *(float2*)&As2[nb][ak + 3][2 * am] = make_float2(aN.w, aN.w);
        *(float4*)&Bs[nb][bk0][bn]      = bN0;
        *(float4*)&Bs[nb][bk0][bn + 64] = bN1;
        __syncthreads();
        buf = nb;
    }
    gemm_compute(As2[buf], Bs[buf], m0, bn, acc);

#pragma unroll
    for (int i = 0; i < 4; i++) {
#pragma unroll
        for (int j = 0; j < 4; j++) {
            int n = n_base + bn + (j & 1) * 2 + (j >> 1) * 64;
            *(float2*)&C[(size_t)(m_base + m0 + i) * N + n] = acc[i][j];
        }
    }
}

// ---------------- weight prep ----------------
// elementwise split (layout preserved): W_ih, W_hh
__global__ void split16(const float* __restrict__ src, __half* __restrict__ dhi,
                        __half* __restrict__ dlo, int n)
{
    int i = blockIdx.x * 256 + threadIdx.x;
    if (i >= n) return;
    float v = src[i];
    __half hi = __float2half(v);
    dhi[i] = hi;
    dlo[i] = __float2half((v - __half2float(hi)) * 1024.f);
}

// transpose + split: src [K][N] -> dst [n][k]: Wq, W1, W2
__global__ void split16T(const float* __restrict__ src, __half* __restrict__ dhi,
                         __half* __restrict__ dlo, int K, int N)
{
    __shared__ float tile[32][33];
    int n0 = blockIdx.x * 32, k0 = blockIdx.y * 32;
    int tx = threadIdx.x, ty = threadIdx.y;
    for (int i = ty; i < 32; i += 8)
        tile[i][tx] = src[(size_t)(k0 + i) * N + n0 + tx];
    __syncthreads();
    for (int i = ty; i < 32; i += 8) {
        float v = tile[tx][i];
        __half hi = __float2half(v);
        size_t o = (size_t)(n0 + i) * K + k0 + tx;
        dhi[o] = hi;
        dlo[o] = __float2half((v - __half2float(hi)) * 1024.f);
    }
}

__global__ void init_state(const float* __restrict__ h0)
{
    int i = blockIdx.x * blockDim.x + threadIdx.x;
    if (i < B_) g_tok[i] = 1;                  // SOS
    if (i < B_ * H_) {
        float v = h0[i];
        g_h[i] = v;
        int m = i >> 9, j = i & 511;
        __half hi = __float2half(v);
        g_h16[m * 512 + j] = hi;
        g_h16[(m + 64) * 512 + j] = __float2half((v - __half2float(hi)) * 1024.f);
    }
}

// ============ fused attention: qW reduce + emb gather + scores + softmax + ctx ============
__global__ void __launch_bounds__(512, 2)
attn_fused(const float* __restrict__ emb, const float* __restrict__ v_att,
           const float* __restrict__ enc)
{
    __shared__ __align__(16) float s_q[A_];
    __shared__ __align__(16) float s_v[A_];
    __shared__ float s_sc[S_];
    __shared__ float s_attn[S_];

    const int b = blockIdx.x;
    const int tid = threadIdx.x;
    const int w = tid >> 5, lane = tid & 31;

    {
        float qs = 0.f;
#pragma unroll
        for (int z = 0; z < 4; z++)
            qs += g_partA[(size_t)z * B_ * A_ + b * A_ + tid];
        s_q[tid] = qs;
        s_v[tid] = v_att[tid];
        int tok = g_tok[b];
        float ev = emb[(size_t)tok * E_ + tid];
        __half eh = __float2half(ev);
        __half el = __float2half((ev - __half2float(eh)) * 1024.f);
        g_rnn16[b * 1024 + tid] = eh;
        g_rnn16[(b + 64) * 1024 + tid] = el;
        g_mlp16[b * 1536 + tid] = eh;
        g_mlp16[(b + 64) * 1536 + tid] = el;
    }
    __syncthreads();

#pragma unroll
    for (int si = 0; si < 4; si++) {
        int s = w * 4 + si;
        const float4* kp = (const float4*)(g_keys + (size_t)(s * B_ + b) * A_);
        float acc = 0.f;
#pragma unroll
        for (int a4 = lane; a4 < A_ / 4; a4 += 32) {
            float4 k4 = kp[a4];
            float4 q4 = *(const float4*)&s_q[a4 * 4];
            float4 v4 = *(const float4*)&s_v[a4 * 4];
            acc += ftanh(q4.x + k4.x) * v4.x + ftanh(q4.y + k4.y) * v4.y
                 + ftanh(q4.z + k4.z) * v4.z + ftanh(q4.w + k4.w) * v4.w;
        }
#pragma unroll
        for (int o = 16; o; o >>= 1) acc += __shfl_xor_sync(0xffffffffu, acc, o);
        if (lane == 0) s_sc[s] = acc;
    }
    __syncthreads();

    if (w == 0) {
        float a0 = s_sc[lane], a1 = s_sc[lane + 32];
        float mx = fmaxf(a0, a1);
#pragma unroll
        for (int o = 16; o; o >>= 1) mx = fmaxf(mx, __shfl_xor_sync(0xffffffffu, mx, o));
        float e0 = __expf(a0 - mx), e1 = __expf(a1 - mx);
        float ss = e0 + e1;
#pragma unroll
        for (int o = 16; o; o >>= 1) ss += __shfl_xor_sync(0xffffffffu, ss, o);
        float inv = __fdividef(1.f, ss);
        s_attn[lane] = e0 * inv;
        s_attn[lane + 32] = e1 * inv;
    }
    __syncthreads();

    {
        int k = tid;
        float acc = 0.f;
        const float* ep = enc + (size_t)b * K_ + k;
#pragma unroll 8
        for (int s2 = 0; s2 < S_; s2++)
            acc += s_attn[s2] * ep[(size_t)s2 * (B_ * K_)];
        __half ch = __float2half(acc);
        __half cl = __float2half((acc - __half2float(ch)) * 1024.f);
        g_rnn16[b * 1024 + 512 + k] = ch;
        g_rnn16[(b + 64) * 1024 + 512 + k] = cl;
        g_mlp16[b * 1536 + 1024 + k] = ch;
        g_mlp16[(b + 64) * 1536 + 1024 + k] = cl;
    }
}

// fused GRU: reduce gi (4 partials) + gh (2 partials) + cell + write h/h16/mlp16
__global__ void gru_fused(const float* __restrict__ b_ih, const float* __restrict__ b_hh)
{
    int idx = blockIdx.x * 256 + threadIdx.x;
    int b = idx >> 9, j = idx & 511;
    float gir = 0.f, giz = 0.f, gin = 0.f, ghr = 0.f, ghz = 0.f, ghn = 0.f;
#pragma unroll
    for (int z = 0; z < 4; z++) {
        const float* pa = g_partA + (size_t)z * B_ * G3H + b * G3H;
        gir += pa[j]; giz += pa[j + H_]; gin += pa[j + 2 * H_];
    }
#pragma unroll
    for (int z = 0; z < 2; z++) {
        const float* pb = g_partB + (size_t)z * B_ * G3H + b * G3H;
        ghr += pb[j]; ghz += pb[j + H_]; ghn += pb[j + 2 * H_];
    }
    gir += b_ih[j]; giz += b_ih[j + H_]; gin += b_ih[j + 2 * H_];
    ghr += b_hh[j]; ghz += b_hh[j + H_]; ghn += b_hh[j + 2 * H_];
    float r  = fsigmoid(gir + ghr);
    float z_ = fsigmoid(giz + ghz);
    float n  = ftanh(gin + r * ghn);
    float h  = g_h[idx];
    float hn = (1.f - z_) * n + z_ * h;
    g_h[idx] = hn;
    __half hh = __float2half(hn);
    __half hl = __float2half((hn - __half2float(hh)) * 1024.f);
    g_h16[b * 512 + j] = hh;
    g_h16[(b + 64) * 512 + j] = hl;
    g_mlp16[b * 1536 + 512 + j] = hh;
    g_mlp16[(b + 64) * 1536 + 512 + j] = hl;
}

// Sum 8 W1 partials + b1, tanh -> fp16 hi/lo rows of g_hid16
__global__ void reduce_h16(const float* __restrict__ part, const float* __restrict__ bias)
{
    int idx = blockIdx.x * 256 + threadIdx.x;   // 64*512
    int m = idx >> 9, j = idx & 511;
    float s = 0.f;
#pragma unroll
    for (int z = 0; z < 8; z++) s += part[(size_t)z * B_ * H_ + idx];
    s += bias[j];
    float h = tanhf(s);
    __half hi = __float2half(h);
    g_hid16[m * 512 + j] = hi;
    g_hid16[(m + 64) * 512 + j] = __float2half((h - __half2float(hi)) * 1024.f);
}

// softmax over vocab from final logits
__global__ void softmax_v(float* __restrict__ out, int t, int T)
{
    int b = blockIdx.x;
    int tid = threadIdx.x;
    const float* lg = g_logits + (size_t)b * V_;
    float* op = out + ((size_t)b * T + t) * V_;
    int lane = tid & 31, w = tid >> 5;

    float bm = -1e30f; int bi = 0;
    for (int v = tid; v < V_; v += 512) {
        float x = lg[v];
        if (x > bm) { bm = x; bi = v; }
    }
    __shared__ float smax[16]; __shared__ int sidx[16]; __shared__ float ssum[16];
#pragma unroll
    for (int o = 16; o; o >>= 1) {
        float om = __shfl_xor_sync(0xffffffffu, bm, o);
        int   oi = __shfl_xor_sync(0xffffffffu, bi, o);
        if (om > bm || (om == bm && oi < bi)) { bm = om; bi = oi; }
    }
    if (!lane) { smax[w] = bm; sidx[w] = bi; }
    __syncthreads();
    if (tid == 0) {
        float M = smax[0]; int I = sidx[0];
        for (int i = 1; i < 16; i++)
            if (smax[i] > M || (smax[i] == M && sidx[i] < I)) { M = smax[i]; I = sidx[i]; }
        smax[0] = M;
        g_tok[b] = I;
    }
    __syncthreads();
    float mx = smax[0];

    float s = 0.f;
    for (int v = tid; v < V_; v += 512) s += __expf(lg[v] - mx);
#pragma unroll
    for (int o = 16; o; o >>= 1) s += __shfl_xor_sync(0xffffffffu, s, o);
    if (!lane) ssum[w] = s;
    __syncthreads();
    if (tid == 0) {
        float tt = 0.f;
        for (int i = 0; i < 16; i++) tt += ssum[i];
        ssum[0] = tt;
    }
    __syncthreads();
    float inv = __fdividef(1.f, ssum[0]);
    for (int v = tid; v < V_; v += 512) op[v] = __expf(lg[v] - mx) * inv;
}

// ---------------- launch ----------------
extern "C" void kernel_launch(void* const* d_in, const int* in_sizes, int n_in,
                              void* d_out, int out_size)
{
    const float* enc   = (const float*)d_in[0];
    const float* h0    = (const float*)d_in[1];
    const float* emb   = (const float*)d_in[2];
    const float* Wq    = (const float*)d_in[3];
    const float* Wk    = (const float*)d_in[4];
    const float* v_att = (const float*)d_in[5];
    const float* W_ih  = (const float*)d_in[6];
    const float* W_hh  = (const float*)d_in[7];
    const float* b_ih  = (const float*)d_in[8];
    const float* b_hh  = (const float*)d_in[9];
    const float* W1    = (const float*)d_in[10];
    const float* b1    = (const float*)d_in[11];
    const float* W2    = (const float*)d_in[12];
    const float* b2    = (const float*)d_in[13];
    float* out = (float*)d_out;
    const int T = out_size / (B_ * V_);

    float *p_keys, *p_partA, *p_partB;
    __half *p_W2h, *p_W2l, *p_Wihh, *p_Wihl, *p_Whhh, *p_Whhl,
           *p_W1h, *p_W1l, *p_Wqh, *p_Wql, *p_rnn16, *p_h16, *p_mlp16;
    cudaGetSymbolAddress((void**)&p_keys,  g_keys);
    cudaGetSymbolAddress((void**)&p_partA, g_partA);
    cudaGetSymbolAddress((void**)&p_partB, g_partB);
    cudaGetSymbolAddress((void**)&p_W2h,   g_W2T_hi);
    cudaGetSymbolAddress((void**)&p_W2l,   g_W2T_lo);
    cudaGetSymbolAddress((void**)&p_Wihh,  g_Wih_hi);
    cudaGetSymbolAddress((void**)&p_Wihl,  g_Wih_lo);
    cudaGetSymbolAddress((void**)&p_Whhh,  g_Whh_hi);
    cudaGetSymbolAddress((void**)&p_Whhl,  g_Whh_lo);
    cudaGetSymbolAddress((void**)&p_W1h,   g_W1T_hi);
    cudaGetSymbolAddress((void**)&p_W1l,   g_W1T_lo);
    cudaGetSymbolAddress((void**)&p_Wqh,   g_WqT_hi);
    cudaGetSymbolAddress((void**)&p_Wql,   g_WqT_lo);
    cudaGetSymbolAddress((void**)&p_rnn16, g_rnn16);
    cudaGetSymbolAddress((void**)&p_h16,   g_h16);
    cudaGetSymbolAddress((void**)&p_mlp16, g_mlp16);

    cudaFuncSetAttribute(logits_fused, cudaFuncAttributeMaxDynamicSharedMemorySize,
                         LG2_SMEM);
    cudaFuncSetAttribute(hmma_small<2>, cudaFuncAttributeMaxDynamicSharedMemorySize,
                         HS_SMEM);
    cudaFuncSetAttribute(hmma_small<3>, cudaFuncAttributeMaxDynamicSharedMemorySize,
                         HS_SMEM);
    cudaFuncSetAttribute(hmma_small<4>, cudaFuncAttributeMaxDynamicSharedMemorySize,
                         HS_SMEM);

    // per-replay prep
    init_state<<<(B_ * H_ + 255) / 256, 256>>>(h0);
    split16<<<G3H * 1024 / 256, 256>>>(W_ih, p_Wihh, p_Wihl, G3H * 1024);
    split16<<<G3H * 512 / 256, 256>>>(W_hh, p_Whhh, p_Whhl, G3H * 512);
    split16T<<<dim3(512 / 32, 512 / 32), dim3(32, 8)>>>(Wq, p_Wqh, p_Wql, 512, 512);
    split16T<<<dim3(512 / 32, 1536 / 32), dim3(32, 8)>>>(W1, p_W1h, p_W1l, 1536, 512);
    split16T<<<dim3(V_ / 32, 512 / 32), dim3(32, 8)>>>(W2, p_W2h, p_W2l, 512, V_);
    gemm64<<<dim3(A_ / 128, (S_ * B_) / 64), 256>>>(enc, Wk, p_keys, K_, A_);

    for (int t = 0; t < T; t++) {
        // qW = h @ Wq (N=512, K=512, splitZ=4, Keff=128)
        hmma_small<2><<<dim3(4, 4), 256, HS_SMEM>>>(p_h16, p_Wqh, p_Wql,
                                                    p_partA, 512, 512);
        attn_fused<<<B_, 512>>>(emb, v_att, enc);

        // gi = rnn_in @ W_ih^T (N=1536, K=1024, splitZ=4, Keff=256)
        hmma_small<4><<<dim3(12, 4), 256, HS_SMEM>>>(p_rnn16, p_Wihh, p_Wihl,
                                                     p_partA, 1024, G3H);
        // gh = h @ W_hh^T (N=1536, K=512, splitZ=2, Keff=256)
        hmma_small<4><<<dim3(12, 2), 256, HS_SMEM>>>(p_h16, p_Whhh, p_Whhl,
                                                     p_partB, 512, G3H);
        gru_fused<<<B_ * H_ / 256, 256>>>(b_ih, b_hh);

        // hidden pre-act = mlp_in @ W1 (N=512, K=1536, splitZ=8, Keff=192)
        hmma_small<3><<<dim3(4, 8), 256, HS_SMEM>>>(p_mlp16, p_W1h, p_W1l,
                                                    p_partA, 1536, 512);
        reduce_h16<<<B_ * H_ / 256, 256>>>(p_partA, b1);

        // logits (hh + lh/1024 + hl/1024 + b2), single wave
        logits_fused<<<125, 256, LG2_SMEM>>>(b2);

        softmax_v<<<B_, 512>>>(out, t, T);
    }
}

// round 10
// speedup vs baseline: 1.1062x; 1.1062x over previous
#include <cuda_runtime.h>
#include <cuda_fp16.h>
#include <math.h>
#include <stdint.h>

#define S_  64
#define B_  64
#define K_  512
#define H_  512
#define E_  512
#define A_  512
#define V_  32000
#define G3H 1536

// ---------------- scratch (static device memory; no allocations) ----------------
__device__ float g_keys[S_ * B_ * A_];
__device__ float g_rnn_in[B_ * (E_ + K_)];
__device__ float g_mlp_in[B_ * (E_ + H_ + K_)];
__device__ float g_h[B_ * H_];
__device__ float g_logits[(size_t)B_ * V_];
__device__ float g_partA[16 * B_ * G3H];
__device__ float g_partB[16 * B_ * G3H];
__device__ float g_WihT[(E_ + K_) * G3H];
__device__ float g_WhhT[H_ * G3H];
__device__ int   g_tok[B_];
// fp16 split operands for the HMMA logits GEMM
__device__ __half g_W2T_hi[(size_t)V_ * 512];   // [n][k]
__device__ __half g_W2T_lo[(size_t)V_ * 512];   // [n][k] (x1024)
__device__ __half g_hid16[128 * 512];           // rows 0-63 hi, 64-127 lo*1024
// per-(row, tile) softmax partials from logits_fused
__device__ float g_tmax[B_ * 125];
__device__ int   g_targ[B_ * 125];
__device__ float g_tsum[B_ * 125];

// ---------------- fast math ----------------
__device__ __forceinline__ float ftanh(float x) {
    float t = __expf(-2.f * fabsf(x));
    float r = __fdividef(1.f - t, 1.f + t);
    return copysignf(r, x);
}
__device__ __forceinline__ float fsigmoid(float x) {
    return __fdividef(1.f, 1.f + __expf(-x));
}

// ---------------- packed f32x2 FMA ----------------
__device__ __forceinline__ float2 ffma2(float2 a, float2 b, float2 c) {
    unsigned long long ua = *reinterpret_cast<unsigned long long*>(&a);
    unsigned long long ub = *reinterpret_cast<unsigned long long*>(&b);
    unsigned long long uc = *reinterpret_cast<unsigned long long*>(&c);
    unsigned long long ud;
    asm("fma.rn.f32x2 %0, %1, %2, %3;" : "=l"(ud) : "l"(ua), "l"(ub), "l"(uc));
    return *reinterpret_cast<float2*>(&ud);
}

// ---------------- baseline-PTX async helpers ----------------
__device__ __forceinline__ uint32_t smem_to_u32(const void* p) {
    uint32_t a;
    asm("{ .reg .u64 t; cvta.to.shared.u64 t, %1; cvt.u32.u64 %0, t; }"
        : "=r"(a) : "l"(p));
    return a;
}
#define MBAR_INIT(mb, c) asm volatile("mbarrier.init.shared.b64 [%0], %1;" :: "r"(mb), "r"((uint32_t)(c)) : "memory")
#define MBAR_ARRIVE_TX(mb, tx) asm volatile("mbarrier.arrive.expect_tx.shared.b64 _, [%0], %1;" :: "r"(mb), "r"((uint32_t)(tx)) : "memory")
#define MBAR_WAIT(mb, par) do {                                              \
    uint32_t _m = (mb), _p = (par), _d;                                      \
    asm volatile("{\n\t.reg .pred p;\n\t"                                    \
        "mbarrier.try_wait.parity.acquire.cta.shared::cta.b64 p, [%1], %2;\n\t" \
        "selp.b32 %0, 1, 0, p;\n\t}" : "=r"(_d) : "r"(_m), "r"(_p) : "memory"); \
    if (!_d) {                                                               \
        asm volatile("{\n\t.reg .pred P1;\n\tWL_%=:\n\t"                     \
            "mbarrier.try_wait.parity.acquire.cta.shared::cta.b64 P1, [%0], %1, 0x989680;\n\t" \
            "@P1 bra.uni WD_%=;\n\tbra.uni WL_%=;\n\tWD_%=:\n\t}"            \
            :: "r"(_m), "r"(_p) : "memory");                                 \
    }                                                                        \
} while (0)

__device__ __forceinline__ void bulk128(uint32_t dst, const void* src, uint32_t mbar) {
    asm volatile(
        "cp.async.bulk.shared::cluster.global.mbarrier::complete_tx::bytes "
        "[%0], [%1], %2, [%3];"
        :: "r"(dst), "l"(src), "r"(128u), "r"(mbar) : "memory");
}
__device__ __forceinline__ void ldsm4(uint32_t& r0, uint32_t& r1, uint32_t& r2,
                                      uint32_t& r3, uint32_t sa) {
    asm volatile("ldmatrix.sync.aligned.m8n8.x4.shared.b16 {%0,%1,%2,%3}, [%4];"
                 : "=r"(r0), "=r"(r1), "=r"(r2), "=r"(r3) : "r"(sa));
}
__device__ __forceinline__ void mma16816(float* c, uint32_t a0, uint32_t a1,
                                         uint32_t a2, uint32_t a3,
                                         uint32_t b0, uint32_t b1) {
    asm volatile(
        "mma.sync.aligned.m16n8k16.row.col.f32.f16.f16.f32 "
        "{%0,%1,%2,%3}, {%4,%5,%6,%7}, {%8,%9}, {%0,%1,%2,%3};"
        : "+f"(c[0]), "+f"(c[1]), "+f"(c[2]), "+f"(c[3])
        : "r"(a0), "r"(a1), "r"(a2), "r"(a3), "r"(b0), "r"(b1));
}

// ============ generic NN GEMM (small): tile 64x128 (round-7, passing) ============
__device__ __forceinline__ void gemm_compute(
    const float (*As2)[130], const float (*Bs)[128],
    int m0, int bn, float2 acc[4][4])
{
#pragma unroll
    for (int kk = 0; kk < 16; kk++) {
        float2 ad[4];
#pragma unroll
        for (int i = 0; i < 4; i++)
            ad[i] = *(const float2*)&As2[kk][2 * (m0 + i)];
        float4 b0 = *(const float4*)&Bs[kk][bn];
        float4 b1 = *(const float4*)&Bs[kk][bn + 64];
        float2 bp[4];
        bp[0] = make_float2(b0.x, b0.y); bp[1] = make_float2(b0.z, b0.w);
        bp[2] = make_float2(b1.x, b1.y); bp[3] = make_float2(b1.z, b1.w);
#pragma unroll
        for (int i = 0; i < 4; i++)
#pragma unroll
            for (int j = 0; j < 4; j++)
                acc[i][j] = ffma2(ad[i], bp[j], acc[i][j]);
    }
}

__global__ void __launch_bounds__(256, 3)
gemm64(const float* __restrict__ A, const float* __restrict__ B,
       float* __restrict__ C, const float* __restrict__ bias,
       int K, int N, int act)
{
    __shared__ __align__(16) float As2[2][16][130];
    __shared__ __align__(16) float Bs[2][16][128];

    const int tid = threadIdx.x;
    const int Keff = K / gridDim.z;
    const float* Ap = A + (size_t)blockIdx.z * Keff;
    const float* Bp = B + (size_t)blockIdx.z * Keff * N;
    float* Cp = C + (size_t)blockIdx.z * 64 * N;

    const int m_base = blockIdx.y * 64;
    const int n_base = blockIdx.x * 128;

    const int ty = tid >> 4, tx = tid & 15;
    const int m0 = ty * 4;
    const int bn = tx * 4;

    const int am = tid >> 2, ak = (tid & 3) * 4;
    const int bk0 = tid >> 4;

    const float* Aload = Ap + (size_t)(m_base + am) * K + ak;
    const float* Bload = Bp + (size_t)bk0 * N + n_base + bn;

    float2 acc[4][4];
#pragma unroll
    for (int i = 0; i < 4; i++)
#pragma unroll
        for (int j = 0; j < 4; j++) acc[i][j] = make_float2(0.f, 0.f);

    float4 aR  = *(const float4*)Aload;
    float4 bR0 = *(const float4*)Bload;
    float4 bR1 = *(const float4*)(Bload + 64);

    *(float2*)&As2[0][ak + 0][2 * am] = make_float2(aR.x, aR.x);
    *(float2*)&As2[0][ak + 1][2 * am] = make_float2(aR.y, aR.y);
    *(float2*)&As2[0][ak + 2][2 * am] = make_float2(aR.z, aR.z);
    *(float2*)&As2[0][ak + 3][2 * am] = make_float2(aR.w, aR.w);
    *(float4*)&Bs[0][bk0][bn]      = bR0;
    *(float4*)&Bs[0][bk0][bn + 64] = bR1;
    __syncthreads();

    int buf = 0;
    for (int k0 = 16; k0 < Keff; k0 += 16) {
        float4 aN  = *(const float4*)(Aload + k0);
        float4 bN0 = *(const float4*)(Bload + (size_t)k0 * N);
        float4 bN1 = *(const float4*)(Bload + (size_t)k0 * N + 64);

        gemm_compute(As2[buf], Bs[buf], m0, bn, acc);

        int nb = buf ^ 1;
        *(float2*)&As2[nb][ak + 0][2 * am] = make_float2(aN.x, aN.x);
        *(float2*)&As2[nb][ak + 1][2 * am] = make_float2(aN.y, aN.y);
        *(float2*)&As2[nb][ak + 2][2 * am] = make_float2(aN.z, aN.z);
        *(float2*)&As2[nb][ak + 3][2 * am] = make_float2(aN.w, aN.w);
        *(float4*)&Bs[nb][bk0][bn]      = bN0;
        *(float4*)&Bs[nb][bk0][bn + 64] = bN1;
        __syncthreads();
        buf = nb;
    }
    gemm_compute(As2[buf], Bs[buf], m0, bn, acc);

#pragma unroll
    for (int i = 0; i < 4; i++) {
#pragma unroll
        for (int j = 0; j < 4; j++) {
            int n = n_base + bn + (j & 1) * 2 + (j >> 1) * 64;
            float2 v = acc[i][j];
            if (bias) { v.x += bias[n]; v.y += bias[n + 1]; }
            if (act)  { v.x = tanhf(v.x); v.y = tanhf(v.y); }
            *(float2*)&Cp[(size_t)(m_base + m0 + i) * N + n] = v;
        }
    }
}

// ============ merged HMMA fp16-split logits GEMM (round-7) + softmax partials ============
#define LG2_AOFF(b) ((b) * 18432)
#define LG2_BOFF(b) (36864 + (b) * 36864)
#define LG2_POFF    110592
#define LG2_PSTR    264
#define LG2_BAR0    178176
#define LG2_BAR1    178184
#define LG2_SMEM    178208

template<int NT>
__device__ __forceinline__ void lg_chunk_compute(
    uint32_t ab, uint32_t bb, int warpM, int warpN, int lane,
    float (&acc)[2][NT][4])
{
#pragma unroll
    for (int kk = 0; kk < 4; kk++) {
        uint32_t af[2][4];
#pragma unroll
        for (int mt = 0; mt < 2; mt++) {
            int row = warpM + mt * 16 + (lane & 15);
            uint32_t sa = ab + row * 144 + kk * 32 + ((lane >> 4) << 4);
            ldsm4(af[mt][0], af[mt][1], af[mt][2], af[mt][3], sa);
        }
#pragma unroll
        for (int np = 0; np < NT / 2; np++) {
            int nr = warpN + np * 16 + (lane & 7) + (((lane >> 4) & 1) << 3);
            uint32_t sbad = bb + nr * 144 + kk * 32 + (((lane >> 3) & 1) << 4);
            uint32_t b0, b1, b2r, b3;
            ldsm4(b0, b1, b2r, b3, sbad);
            mma16816(acc[0][2 * np],     af[0][0], af[0][1], af[0][2], af[0][3], b0, b1);
            mma16816(acc[1][2 * np],     af[1][0], af[1][1], af[1][2], af[1][3], b0, b1);
            mma16816(acc[0][2 * np + 1], af[0][0], af[0][1], af[0][2], af[0][3], b2r, b3);
            mma16816(acc[1][2 * np + 1], af[1][0], af[1][1], af[1][2], af[1][3], b2r, b3);
        }
    }
}

__global__ void __launch_bounds__(256, 1)
logits_fused(const float* __restrict__ b2)
{
    extern __shared__ __align__(16) char sm[];
    const uint32_t sb = smem_to_u32(sm);
    const int tid = threadIdx.x;
    const int w = tid >> 5, lane = tid & 31;
    const int n_base = blockIdx.x * 256;
    float* P = (float*)(sm + LG2_POFF);
    const float IS = 0.0009765625f;
    const int g = lane >> 2, tq = lane & 3;

    if (tid == 0) { MBAR_INIT(sb + LG2_BAR0, 256); MBAR_INIT(sb + LG2_BAR1, 256); }
    __syncthreads();
    int ph0 = 0, ph1 = 0;

    // pass 1: [hid_hi; hid_lo*1024] (M=128) x W2T_hi
    {
        const int wm = w >> 1;
        const int warpM = wm * 32, warpN = (w & 1) * 128;
        float acc[2][16][4];
#pragma unroll
        for (int i = 0; i < 2; i++)
#pragma unroll
            for (int j = 0; j < 16; j++)
#pragma unroll
                for (int q = 0; q < 4; q++) acc[i][j][q] = 0.f;

        {
            uint32_t bar = sb + LG2_BAR0;
            int myA = (tid < 128) ? 1 : 0;
            MBAR_ARRIVE_TX(bar, 128u * (1 + myA));
            bulk128(sb + LG2_BOFF(0) + tid * 144,
                    g_W2T_hi + (size_t)(n_base + tid) * 512, bar);
            if (myA)
                bulk128(sb + LG2_AOFF(0) + tid * 144, g_hid16 + tid * 512, bar);
        }
        for (int c = 0; c < 8; c++) {
            const int buf = c & 1;
            if (c + 1 < 8) {
                uint32_t bar = sb + ((buf ^ 1) ? LG2_BAR1 : LG2_BAR0);
                int myA = (tid < 128) ? 1 : 0;
                MBAR_ARRIVE_TX(bar, 128u * (1 + myA));
                bulk128(sb + LG2_BOFF(buf ^ 1) + tid * 144,
                        g_W2T_hi + (size_t)(n_base + tid) * 512 + (c + 1) * 64, bar);
                if (myA)
                    bulk128(sb + LG2_AOFF(buf ^ 1) + tid * 144,
                            g_hid16 + tid * 512 + (c + 1) * 64, bar);
            }
            if (buf == 0) { MBAR_WAIT(sb + LG2_BAR0, ph0); ph0 ^= 1; }
            else          { MBAR_WAIT(sb + LG2_BAR1, ph1); ph1 ^= 1; }
            __syncthreads();
            lg_chunk_compute<16>(sb + LG2_AOFF(buf), sb + LG2_BOFF(buf),
                                 warpM, warpN, lane, acc);
            __syncthreads();
        }
        if (wm >= 2) {
#pragma unroll
            for (int mt = 0; mt < 2; mt++) {
                int m = warpM - 64 + mt * 16 + g;
#pragma unroll
                for (int nt = 0; nt < 16; nt++) {
                    int col = warpN + nt * 8 + tq * 2;
                    P[m * LG2_PSTR + col]           = acc[mt][nt][0] * IS;
                    P[m * LG2_PSTR + col + 1]       = acc[mt][nt][1] * IS;
                    P[(m + 8) * LG2_PSTR + col]     = acc[mt][nt][2] * IS;
                    P[(m + 8) * LG2_PSTR + col + 1] = acc[mt][nt][3] * IS;
                }
            }
        }
        __syncthreads();
        if (wm < 2) {
#pragma unroll
            for (int mt = 0; mt < 2; mt++) {
                int m = warpM + mt * 16 + g;
#pragma unroll
                for (int nt = 0; nt < 16; nt++) {
                    int col = warpN + nt * 8 + tq * 2;
                    P[m * LG2_PSTR + col]           += acc[mt][nt][0];
                    P[m * LG2_PSTR + col + 1]       += acc[mt][nt][1];
                    P[(m + 8) * LG2_PSTR + col]     += acc[mt][nt][2];
                    P[(m + 8) * LG2_PSTR + col + 1] += acc[mt][nt][3];
                }
            }
        }
        __syncthreads();
    }

    // pass 2: hid_hi (M=64) x W2T_lo*1024
    {
        const int warpM = (w >> 2) * 32, warpN = (w & 3) * 64;
        float acc[2][8][4];
#pragma unroll
        for (int i = 0; i < 2; i++)
#pragma unroll
            for (int j = 0; j < 8; j++)
#pragma unroll
                for (int q = 0; q < 4; q++) acc[i][j][q] = 0.f;

        {
            uint32_t bar = sb + LG2_BAR0;
            int myA = (tid < 64) ? 1 : 0;
            MBAR_ARRIVE_TX(bar, 128u * (1 + myA));
            bulk128(sb + LG2_BOFF(0) + tid * 144,
                    g_W2T_lo + (size_t)(n_base + tid) * 512, bar);
            if (myA)
                bulk128(sb + LG2_AOFF(0) + tid * 144, g_hid16 + tid * 512, bar);
        }
        for (int c = 0; c < 8; c++) {
            const int buf = c & 1;
            if (c + 1 < 8) {
                uint32_t bar = sb + ((buf ^ 1) ? LG2_BAR1 : LG2_BAR0);
                int myA = (tid < 64) ? 1 : 0;
                MBAR_ARRIVE_TX(bar, 128u * (1 + myA));
                bulk128(sb + LG2_BOFF(buf ^ 1) + tid * 144,
                        g_W2T_lo + (size_t)(n_base + tid) * 512 + (c + 1) * 64, bar);
                if (myA)
                    bulk128(sb + LG2_AOFF(buf ^ 1) + tid * 144,
                            g_hid16 + tid * 512 + (c + 1) * 64, bar);
            }
            if (buf == 0) { MBAR_WAIT(sb + LG2_BAR0, ph0); ph0 ^= 1; }
            else          { MBAR_WAIT(sb + LG2_BAR1, ph1); ph1 ^= 1; }
            __syncthreads();
            lg_chunk_compute<8>(sb + LG2_AOFF(buf), sb + LG2_BOFF(buf),
                                warpM, warpN, lane, acc);
            __syncthreads();
        }
#pragma unroll
        for (int mt = 0; mt < 2; mt++) {
            int m = warpM + mt * 16 + g;
#pragma unroll
            for (int nt = 0; nt < 8; nt++) {
                int col = warpN + nt * 8 + tq * 2;
                P[m * LG2_PSTR + col]           += acc[mt][nt][0] * IS;
                P[m * LG2_PSTR + col + 1]       += acc[mt][nt][1] * IS;
                P[(m + 8) * LG2_PSTR + col]     += acc[mt][nt][2] * IS;
                P[(m + 8) * LG2_PSTR + col + 1] += acc[mt][nt][3] * IS;
            }
        }
        __syncthreads();
    }

    // write final logits + bias, keep biased values in P for the stats phase
    for (int i = tid; i < 64 * 64; i += 256) {
        int m = i >> 6;
        int c4 = (i & 63) * 4;
        float4 p = *(float4*)&P[m * LG2_PSTR + c4];
        float4 bb = *(const float4*)&b2[n_base + c4];
        p.x += bb.x; p.y += bb.y; p.z += bb.z; p.w += bb.w;
        *(float4*)&P[m * LG2_PSTR + c4] = p;
        *(float4*)&g_logits[(size_t)m * V_ + n_base + c4] = p;
    }
    __syncthreads();

    // per-(row, tile) softmax partials: max / argmax / sum-exp over 256 cols
    {
        float* s_qmax = (float*)sm;            // [64][4]
        int*   s_qarg = (int*)(sm + 1024);     // [64][4]
        float* s_rmax = (float*)(sm + 2048);   // [64]
        float* s_qsum = (float*)(sm + 2304);   // [64][4]
        int m = tid >> 2, q = tid & 3;
        const float* Pr = &P[m * LG2_PSTR + q * 64];
        float mx = -1e30f; int ai = 0;
#pragma unroll 8
        for (int c = 0; c < 64; c++) {
            float x = Pr[c];
            if (x > mx) { mx = x; ai = q * 64 + c; }
        }
        s_qmax[m * 4 + q] = mx; s_qarg[m * 4 + q] = ai;
        __syncthreads();
        if (q == 0) {
            float M = s_qmax[m * 4]; int I = s_qarg[m * 4];
#pragma unroll
            for (int j = 1; j < 4; j++) {
                float om = s_qmax[m * 4 + j]; int oi = s_qarg[m * 4 + j];
                if (om > M || (om == M && oi < I)) { M = om; I = oi; }
            }
            s_rmax[m] = M;
            g_tmax[m * 125 + blockIdx.x] = M;
            g_targ[m * 125 + blockIdx.x] = n_base + I;
        }
        __syncthreads();
        float tm = s_rmax[m];
        float se = 0.f;
#pragma unroll 8
        for (int c = 0; c < 64; c++) se += __expf(Pr[c] - tm);
        s_qsum[m * 4 + q] = se;
        __syncthreads();
        if (q == 0)
            g_tsum[m * 125 + blockIdx.x] =
                s_qsum[m * 4] + s_qsum[m * 4 + 1] + s_qsum[m * 4 + 2] + s_qsum[m * 4 + 3];
    }
}

// prep: W2[k][n] fp32 -> W2T_hi/lo[n][k] fp16 (lo scaled x1024)
__global__ void conv_w2(const float* __restrict__ W2)
{
    __shared__ float tile[32][33];
    int n0 = blockIdx.x * 32, k0 = blockIdx.y * 32;
    int tx = threadIdx.x, ty = threadIdx.y;
    for (int i = ty; i < 32; i += 8)
        tile[i][tx] = W2[(size_t)(k0 + i) * V_ + n0 + tx];
    __syncthreads();
    for (int i = ty; i < 32; i += 8) {
        float wv = tile[tx][i];
        __half hi = __float2half(wv);
        __half lo = __float2half((wv - __half2float(hi)) * 1024.f);
        size_t o = (size_t)(n0 + i) * 512 + k0 + tx;
        g_W2T_hi[o] = hi;
        g_W2T_lo[o] = lo;
    }
}

// Sum split-K partials of W1, + b1, tanh -> fp16 hi/lo rows of g_hid16
__global__ void reduce_h16(const float* __restrict__ part, const float* __restrict__ bias)
{
    int idx = blockIdx.x * 256 + threadIdx.x;   // 64*512
    int m = idx >> 9, j = idx & 511;
    float s = 0.f;
#pragma unroll
    for (int z = 0; z < 32; z++) s += part[(size_t)z * B_ * H_ + idx];
    s += bias[j];
    float h = tanhf(s);
    __half hi = __float2half(h);
    g_hid16[m * 512 + j] = hi;
    g_hid16[(m + 64) * 512 + j] = __float2half((h - __half2float(hi)) * 1024.f);
}

// out[c][r] = in[r][c]
__global__ void transpose_k(const float* __restrict__ in, float* __restrict__ out,
                            int R, int C)
{
    __shared__ float tile[32][33];
    int c = blockIdx.x * 32 + threadIdx.x;
    int r0 = blockIdx.y * 32;
    for (int i = threadIdx.y; i < 32; i += 8)
        tile[i][threadIdx.x] = in[(size_t)(r0 + i) * C + c];
    __syncthreads();
    int r2 = blockIdx.y * 32 + threadIdx.x;
    int c0 = blockIdx.x * 32;
    for (int i = threadIdx.y; i < 32; i += 8)
        out[(size_t)(c0 + i) * R + r2] = tile[threadIdx.x][i];
}

__global__ void init_state(const float* __restrict__ h0)
{
    int i = blockIdx.x * blockDim.x + threadIdx.x;
    if (i < B_) g_tok[i] = 1;                  // SOS
    if (i < B_ * H_) g_h[i] = h0[i];
}

// ============ fused attention (round-7, passing) ============
__global__ void __launch_bounds__(512, 2)
attn_fused(const float* __restrict__ emb, const float* __restrict__ v_att,
           const float* __restrict__ enc)
{
    __shared__ __align__(16) float s_q[A_];
    __shared__ __align__(16) float s_v[A_];
    __shared__ float s_sc[S_];
    __shared__ float s_attn[S_];

    const int b = blockIdx.x;
    const int tid = threadIdx.x;
    const int w = tid >> 5, lane = tid & 31;

    {
        float qs = 0.f;
#pragma unroll
        for (int z = 0; z < 16; z++)
            qs += g_partA[(size_t)z * B_ * A_ + b * A_ + tid];
        s_q[tid] = qs;
        s_v[tid] = v_att[tid];
        int tok = g_tok[b];
        float ev = emb[(size_t)tok * E_ + tid];
        g_rnn_in[b * (E_ + K_) + tid] = ev;
        g_mlp_in[b * (E_ + H_ + K_) + tid] = ev;
    }
    __syncthreads();

#pragma unroll
    for (int si = 0; si < 4; si++) {
        int s = w * 4 + si;
        const float4* kp = (const float4*)(g_keys + (size_t)(s * B_ + b) * A_);
        float acc = 0.f;
#pragma unroll
        for (int a4 = lane; a4 < A_ / 4; a4 += 32) {
            float4 k4 = kp[a4];
            float4 q4 = *(const float4*)&s_q[a4 * 4];
            float4 v4 = *(const float4*)&s_v[a4 * 4];
            acc += ftanh(q4.x + k4.x) * v4.x + ftanh(q4.y + k4.y) * v4.y
                 + ftanh(q4.z + k4.z) * v4.z + ftanh(q4.w + k4.w) * v4.w;
        }
#pragma unroll
        for (int o = 16; o; o >>= 1) acc += __shfl_xor_sync(0xffffffffu, acc, o);
        if (lane == 0) s_sc[s] = acc;
    }
    __syncthreads();

    if (w == 0) {
        float a0 = s_sc[lane], a1 = s_sc[lane + 32];
        float mx = fmaxf(a0, a1);
#pragma unroll
        for (int o = 16; o; o >>= 1) mx = fmaxf(mx, __shfl_xor_sync(0xffffffffu, mx, o));
        float e0 = __expf(a0 - mx), e1 = __expf(a1 - mx);
        float ss = e0 + e1;
#pragma unroll
        for (int o = 16; o; o >>= 1) ss += __shfl_xor_sync(0xffffffffu, ss, o);
        float inv = __fdividef(1.f, ss);
        s_attn[lane] = e0 * inv;
        s_attn[lane + 32] = e1 * inv;
    }
    __syncthreads();

    {
        int k = tid;
        float acc = 0.f;
        const float* ep = enc + (size_t)b * K_ + k;
#pragma unroll 8
        for (int s2 = 0; s2 < S_; s2++)
            acc += s_attn[s2] * ep[(size_t)s2 * (B_ * K_)];
        g_rnn_in[b * (E_ + K_) + E_ + k] = acc;
        g_mlp_in[b * (E_ + H_ + K_) + E_ + H_ + k] = acc;
    }
}

// fused GRU (round-7, passing)
__global__ void gru_fused(const float* __restrict__ b_ih, const float* __restrict__ b_hh)
{
    int idx = blockIdx.x * 256 + threadIdx.x;
    int b = idx >> 9, j = idx & 511;
    float gir = 0.f, giz = 0.f, gin = 0.f, ghr = 0.f, ghz = 0.f, ghn = 0.f;
#pragma unroll
    for (int z = 0; z < 16; z++) {
        const float* pa = g_partA + (size_t)z * B_ * G3H + b * G3H;
        const float* pb = g_partB + (size_t)z * B_ * G3H + b * G3H;
        gir += pa[j]; giz += pa[j + H_]; gin += pa[j + 2 * H_];
        ghr += pb[j]; ghz += pb[j + H_]; ghn += pb[j + 2 * H_];
    }
    gir += b_ih[j]; giz += b_ih[j + H_]; gin += b_ih[j + 2 * H_];
    ghr += b_hh[j]; ghz += b_hh[j + H_]; ghn += b_hh[j + 2 * H_];
    float r  = fsigmoid(gir + ghr);
    float z_ = fsigmoid(giz + ghz);
    float n  = ftanh(gin + r * ghn);
    float h  = g_h[idx];
    float hn = (1.f - z_) * n + z_ * h;
    g_h[idx] = hn;
    g_mlp_in[b * (E_ + H_ + K_) + E_ + j] = hn;
}

// softmax finish: combine 125 tile partials, then one read+write pass
__global__ void __launch_bounds__(512, 2)
softmax_write(float* __restrict__ out, int t, int T)
{
    int b = blockIdx.x;
    int tid = threadIdx.x;
    int lane = tid & 31, w = tid >> 5;
    __shared__ float sM[16]; __shared__ int sI[16]; __shared__ float sS[16];
    __shared__ float fM, fInv;

    float bm = -1e30f; int bi = 0;
    if (tid < 125) { bm = g_tmax[b * 125 + tid]; bi = g_targ[b * 125 + tid]; }
#pragma unroll
    for (int o = 16; o; o >>= 1) {
        float om = __shfl_xor_sync(0xffffffffu, bm, o);
        int   oi = __shfl_xor_sync(0xffffffffu, bi, o);
        if (om > bm || (om == bm && oi < bi)) { bm = om; bi = oi; }
    }
    if (!lane) { sM[w] = bm; sI[w] = bi; }
    __syncthreads();
    if (tid == 0) {
        float M = sM[0]; int I = sI[0];
        for (int i = 1; i < 16; i++)
            if (sM[i] > M || (sM[i] == M && sI[i] < I)) { M = sM[i]; I = sI[i]; }
        fM = M;
        g_tok[b] = I;
    }
    __syncthreads();
    float M = fM;

    float s = 0.f;
    if (tid < 125) s = g_tsum[b * 125 + tid] * __expf(g_tmax[b * 125 + tid] - M);
#pragma unroll
    for (int o = 16; o; o >>= 1) s += __shfl_xor_sync(0xffffffffu, s, o);
    if (!lane) sS[w] = s;
    __syncthreads();
    if (tid == 0) {
        float tt = 0.f;
        for (int i = 0; i < 16; i++) tt += sS[i];
        fInv = __fdividef(1.f, tt);
    }
    __syncthreads();
    float inv = fInv;

    const float* lg = g_logits + (size_t)b * V_;
    float* op = out + ((size_t)b * T + t) * V_;
    for (int v = tid; v < V_; v += 512) op[v] = __expf(lg[v] - M) * inv;
}

// ---------------- launch ----------------
extern "C" void kernel_launch(void* const* d_in, const int* in_sizes, int n_in,
                              void* d_out, int out_size)
{
    const float* enc   = (const float*)d_in[0];
    const float* h0    = (const float*)d_in[1];
    const float* emb   = (const float*)d_in[2];
    const float* Wq    = (const float*)d_in[3];
    const float* Wk    = (const float*)d_in[4];
    const float* v_att = (const float*)d_in[5];
    const float* W_ih  = (const float*)d_in[6];
    const float* W_hh  = (const float*)d_in[7];
    const float* b_ih  = (const float*)d_in[8];
    const float* b_hh  = (const float*)d_in[9];
    const float* W1    = (const float*)d_in[10];
    const float* b1    = (const float*)d_in[11];
    const float* W2    = (const float*)d_in[12];
    const float* b2    = (const float*)d_in[13];
    float* out = (float*)d_out;
    const int T = out_size / (B_ * V_);

    float *p_keys, *p_rnn, *p_mlp, *p_h, *p_partA, *p_partB, *p_WihT, *p_WhhT;
    cudaGetSymbolAddress((void**)&p_keys,   g_keys);
    cudaGetSymbolAddress((void**)&p_rnn,    g_rnn_in);
    cudaGetSymbolAddress((void**)&p_mlp,    g_mlp_in);
    cudaGetSymbolAddress((void**)&p_h,      g_h);
    cudaGetSymbolAddress((void**)&p_partA,  g_partA);
    cudaGetSymbolAddress((void**)&p_partB,  g_partB);
    cudaGetSymbolAddress((void**)&p_WihT,   g_WihT);
    cudaGetSymbolAddress((void**)&p_WhhT,   g_WhhT);

    cudaFuncSetAttribute(logits_fused, cudaFuncAttributeMaxDynamicSharedMemorySize,
                         LG2_SMEM);

    // per-replay prep
    init_state<<<(B_ * H_ + 255) / 256, 256>>>(h0);
    transpose_k<<<dim3((E_ + K_) / 32, G3H / 32), dim3(32, 8)>>>(W_ih, p_WihT, G3H, E_ + K_);
    transpose_k<<<dim3(H_ / 32, G3H / 32), dim3(32, 8)>>>(W_hh, p_WhhT, G3H, H_);
    conv_w2<<<dim3(V_ / 32, 512 / 32), dim3(32, 8)>>>(W2);
    gemm64<<<dim3(A_ / 128, (S_ * B_) / 64, 1), 256>>>(enc, Wk, p_keys, nullptr, K_, A_, 0);

    for (int t = 0; t < T; t++) {
        // qW = h @ Wq (split-K x16 -> partA)
        gemm64<<<dim3(A_ / 128, 1, 16), 256>>>(p_h, Wq, p_partA, nullptr, H_, A_, 0);
        attn_fused<<<B_, 512>>>(emb, v_att, enc);

        // gi = rnn_in @ W_ih^T (x16) ; gh = h @ W_hh^T (x16)
        gemm64<<<dim3(G3H / 128, 1, 16), 256>>>(p_rnn, p_WihT, p_partA, nullptr, E_ + K_, G3H, 0);
        gemm64<<<dim3(G3H / 128, 1, 16), 256>>>(p_h, p_WhhT, p_partB, nullptr, H_, G3H, 0);
        gru_fused<<<B_ * H_ / 256, 256>>>(b_ih, b_hh);

        // hidden = tanh(mlp_in @ W1 + b1) -> fp16 hi/lo (split-K x32)
        gemm64<<<dim3(H_ / 128, 1, 32), 256>>>(p_mlp, W1, p_partA, nullptr, E_ + H_ + K_, H_, 0);
        reduce_h16<<<B_ * H_ / 256, 256>>>(p_partA, b1);

        // logits + per-tile softmax partials, single wave
        logits_fused<<<125, 256, LG2_SMEM>>>(b2);

        // combine partials + single output pass
        softmax_write<<<B_, 512>>>(out, t, T);
    }
}

// round 11
// speedup vs baseline: 1.1725x; 1.0599x over previous
#include <cuda_runtime.h>
#include <cuda_fp16.h>
#include <math.h>
#include <stdint.h>

#define S_  64
#define B_  64
#define K_  512
#define H_  512
#define E_  512
#define A_  512
#define V_  32000
#define G3H 1536

// ---------------- scratch (static device memory; no allocations) ----------------
__device__ float g_keys[S_ * B_ * A_];
__device__ float g_rnn_in[B_ * (E_ + K_)];
__device__ float g_mlp_in[B_ * (E_ + H_ + K_)];
__device__ float g_h[B_ * H_];
__device__ float g_logits[(size_t)B_ * V_];
__device__ float g_partA[16 * B_ * G3H];
__device__ float g_partB[16 * B_ * G3H];
__device__ float g_WihT[(E_ + K_) * G3H];
__device__ float g_WhhT[H_ * G3H];
__device__ int   g_tok[B_];
// fp16 split operands for the HMMA logits GEMM
__device__ __half g_W2T_hi[(size_t)V_ * 512];   // [n][k]
__device__ __half g_W2T_lo[(size_t)V_ * 512];   // [n][k] (x1024)
__device__ __half g_hid16[128 * 512];           // rows 0-63 hi, 64-127 lo*1024
// per-(b, slice) softmax partials (4 slices of 8000)
__device__ float g_smax[B_ * 4];
__device__ int   g_sarg[B_ * 4];
__device__ float g_ssum[B_ * 4];

// ---------------- fast math ----------------
__device__ __forceinline__ float ftanh(float x) {
    float t = __expf(-2.f * fabsf(x));
    float r = __fdividef(1.f - t, 1.f + t);
    return copysignf(r, x);
}
__device__ __forceinline__ float fsigmoid(float x) {
    return __fdividef(1.f, 1.f + __expf(-x));
}

// ---------------- packed f32x2 FMA ----------------
__device__ __forceinline__ float2 ffma2(float2 a, float2 b, float2 c) {
    unsigned long long ua = *reinterpret_cast<unsigned long long*>(&a);
    unsigned long long ub = *reinterpret_cast<unsigned long long*>(&b);
    unsigned long long uc = *reinterpret_cast<unsigned long long*>(&c);
    unsigned long long ud;
    asm("fma.rn.f32x2 %0, %1, %2, %3;" : "=l"(ud) : "l"(ua), "l"(ub), "l"(uc));
    return *reinterpret_cast<float2*>(&ud);
}

// ---------------- baseline-PTX async helpers ----------------
__device__ __forceinline__ uint32_t smem_to_u32(const void* p) {
    uint32_t a;
    asm("{ .reg .u64 t; cvta.to.shared.u64 t, %1; cvt.u32.u64 %0, t; }"
        : "=r"(a) : "l"(p));
    return a;
}
#define MBAR_INIT(mb, c) asm volatile("mbarrier.init.shared.b64 [%0], %1;" :: "r"(mb), "r"((uint32_t)(c)) : "memory")
#define MBAR_ARRIVE_TX(mb, tx) asm volatile("mbarrier.arrive.expect_tx.shared.b64 _, [%0], %1;" :: "r"(mb), "r"((uint32_t)(tx)) : "memory")
#define MBAR_WAIT(mb, par) do {                                              \
    uint32_t _m = (mb), _p = (par), _d;                                      \
    asm volatile("{\n\t.reg .pred p;\n\t"                                    \
        "mbarrier.try_wait.parity.acquire.cta.shared::cta.b64 p, [%1], %2;\n\t" \
        "selp.b32 %0, 1, 0, p;\n\t}" : "=r"(_d) : "r"(_m), "r"(_p) : "memory"); \
    if (!_d) {                                                               \
        asm volatile("{\n\t.reg .pred P1;\n\tWL_%=:\n\t"                     \
            "mbarrier.try_wait.parity.acquire.cta.shared::cta.b64 P1, [%0], %1, 0x989680;\n\t" \
            "@P1 bra.uni WD_%=;\n\tbra.uni WL_%=;\n\tWD_%=:\n\t}"            \
            :: "r"(_m), "r"(_p) : "memory");                                 \
    }                                                                        \
} while (0)

__device__ __forceinline__ void bulk128(uint32_t dst, const void* src, uint32_t mbar) {
    asm volatile(
        "cp.async.bulk.shared::cluster.global.mbarrier::complete_tx::bytes "
        "[%0], [%1], %2, [%3];"
        :: "r"(dst), "l"(src), "r"(128u), "r"(mbar) : "memory");
}
__device__ __forceinline__ void ldsm4(uint32_t& r0, uint32_t& r1, uint32_t& r2,
                                      uint32_t& r3, uint32_t sa) {
    asm volatile("ldmatrix.sync.aligned.m8n8.x4.shared.b16 {%0,%1,%2,%3}, [%4];"
                 : "=r"(r0), "=r"(r1), "=r"(r2), "=r"(r3) : "r"(sa));
}
__device__ __forceinline__ void mma16816(float* c, uint32_t a0, uint32_t a1,
                                         uint32_t a2, uint32_t a3,
                                         uint32_t b0, uint32_t b1) {
    asm volatile(
        "mma.sync.aligned.m16n8k16.row.col.f32.f16.f16.f32 "
        "{%0,%1,%2,%3}, {%4,%5,%6,%7}, {%8,%9}, {%0,%1,%2,%3};"
        : "+f"(c[0]), "+f"(c[1]), "+f"(c[2]), "+f"(c[3])
        : "r"(a0), "r"(a1), "r"(a2), "r"(a3), "r"(b0), "r"(b1));
}

// ============ generic NN GEMM (small): tile 64x128 (round-7, passing) ============
__device__ __forceinline__ void gemm_compute(
    const float (*As2)[130], const float (*Bs)[128],
    int m0, int bn, float2 acc[4][4])
{
#pragma unroll
    for (int kk = 0; kk < 16; kk++) {
        float2 ad[4];
#pragma unroll
        for (int i = 0; i < 4; i++)
            ad[i] = *(const float2*)&As2[kk][2 * (m0 + i)];
        float4 b0 = *(const float4*)&Bs[kk][bn];
        float4 b1 = *(const float4*)&Bs[kk][bn + 64];
        float2 bp[4];
        bp[0] = make_float2(b0.x, b0.y); bp[1] = make_float2(b0.z, b0.w);
        bp[2] = make_float2(b1.x, b1.y); bp[3] = make_float2(b1.z, b1.w);
#pragma unroll
        for (int i = 0; i < 4; i++)
#pragma unroll
            for (int j = 0; j < 4; j++)
                acc[i][j] = ffma2(ad[i], bp[j], acc[i][j]);
    }
}

__global__ void __launch_bounds__(256, 3)
gemm64(const float* __restrict__ A, const float* __restrict__ B,
       float* __restrict__ C, const float* __restrict__ bias,
       int K, int N, int act)
{
    __shared__ __align__(16) float As2[2][16][130];
    __shared__ __align__(16) float Bs[2][16][128];

    const int tid = threadIdx.x;
    const int Keff = K / gridDim.z;
    const float* Ap = A + (size_t)blockIdx.z * Keff;
    const float* Bp = B + (size_t)blockIdx.z * Keff * N;
    float* Cp = C + (size_t)blockIdx.z * 64 * N;

    const int m_base = blockIdx.y * 64;
    const int n_base = blockIdx.x * 128;

    const int ty = tid >> 4, tx = tid & 15;
    const int m0 = ty * 4;
    const int bn = tx * 4;

    const int am = tid >> 2, ak = (tid & 3) * 4;
    const int bk0 = tid >> 4;

    const float* Aload = Ap + (size_t)(m_base + am) * K + ak;
    const float* Bload = Bp + (size_t)bk0 * N + n_base + bn;

    float2 acc[4][4];
#pragma unroll
    for (int i = 0; i < 4; i++)
#pragma unroll
        for (int j = 0; j < 4; j++) acc[i][j] = make_float2(0.f, 0.f);

    float4 aR  = *(const float4*)Aload;
    float4 bR0 = *(const float4*)Bload;
    float4 bR1 = *(const float4*)(Bload + 64);

    *(float2*)&As2[0][ak + 0][2 * am] = make_float2(aR.x, aR.x);
    *(float2*)&As2[0][ak + 1][2 * am] = make_float2(aR.y, aR.y);
    *(float2*)&As2[0][ak + 2][2 * am] = make_float2(aR.z, aR.z);
    *(float2*)&As2[0][ak + 3][2 * am] = make_float2(aR.w, aR.w);
    *(float4*)&Bs[0][bk0][bn]      = bR0;
    *(float4*)&Bs[0][bk0][bn + 64] = bR1;
    __syncthreads();

    int buf = 0;
    for (int k0 = 16; k0 < Keff; k0 += 16) {
        float4 aN  = *(const float4*)(Aload + k0);
        float4 bN0 = *(const float4*)(Bload + (size_t)k0 * N);
        float4 bN1 = *(const float4*)(Bload + (size_t)k0 * N + 64);

        gemm_compute(As2[buf], Bs[buf], m0, bn, acc);

        int nb = buf ^ 1;
        *(float2*)&As2[nb][ak + 0][2 * am] = make_float2(aN.x, aN.x);
        *(float2*)&As2[nb][ak + 1][2 * am] = make_float2(aN.y, aN.y);
        *(float2*)&As2[nb][ak + 2][2 * am] = make_float2(aN.z, aN.z);
        *(float2*)&As2[nb][ak + 3][2 * am] = make_float2(aN.w, aN.w);
        *(float4*)&Bs[nb][bk0][bn]      = bN0;
        *(float4*)&Bs[nb][bk0][bn + 64] = bN1;
        __syncthreads();
        buf = nb;
    }
    gemm_compute(As2[buf], Bs[buf], m0, bn, acc);

#pragma unroll
    for (int i = 0; i < 4; i++) {
#pragma unroll
        for (int j = 0; j < 4; j++) {
            int n = n_base + bn + (j & 1) * 2 + (j >> 1) * 64;
            float2 v = acc[i][j];
            if (bias) { v.x += bias[n]; v.y += bias[n + 1]; }
            if (act)  { v.x = tanhf(v.x); v.y = tanhf(v.y); }
            *(float2*)&Cp[(size_t)(m_base + m0 + i) * N + n] = v;
        }
    }
}

// ============ merged HMMA fp16-split logits GEMM (round-7, passing) ============
#define LG2_AOFF(b) ((b) * 18432)
#define LG2_BOFF(b) (36864 + (b) * 36864)
#define LG2_POFF    110592
#define LG2_PSTR    264
#define LG2_BAR0    178176
#define LG2_BAR1    178184
#define LG2_SMEM    178208

template<int NT>
__device__ __forceinline__ void lg_chunk_compute(
    uint32_t ab, uint32_t bb, int warpM, int warpN, int lane,
    float (&acc)[2][NT][4])
{
#pragma unroll
    for (int kk = 0; kk < 4; kk++) {
        uint32_t af[2][4];
#pragma unroll
        for (int mt = 0; mt < 2; mt++) {
            int row = warpM + mt * 16 + (lane & 15);
            uint32_t sa = ab + row * 144 + kk * 32 + ((lane >> 4) << 4);
            ldsm4(af[mt][0], af[mt][1], af[mt][2], af[mt][3], sa);
        }
#pragma unroll
        for (int np = 0; np < NT / 2; np++) {
            int nr = warpN + np * 16 + (lane & 7) + (((lane >> 4) & 1) << 3);
            uint32_t sbad = bb + nr * 144 + kk * 32 + (((lane >> 3) & 1) << 4);
            uint32_t b0, b1, b2r, b3;
            ldsm4(b0, b1, b2r, b3, sbad);
            mma16816(acc[0][2 * np],     af[0][0], af[0][1], af[0][2], af[0][3], b0, b1);
            mma16816(acc[1][2 * np],     af[1][0], af[1][1], af[1][2], af[1][3], b0, b1);
            mma16816(acc[0][2 * np + 1], af[0][0], af[0][1], af[0][2], af[0][3], b2r, b3);
            mma16816(acc[1][2 * np + 1], af[1][0], af[1][1], af[1][2], af[1][3], b2r, b3);
        }
    }
}

__global__ void __launch_bounds__(256, 1)
logits_fused(const float* __restrict__ b2)
{
    extern __shared__ __align__(16) char sm[];
    const uint32_t sb = smem_to_u32(sm);
    const int tid = threadIdx.x;
    const int w = tid >> 5, lane = tid & 31;
    const int n_base = blockIdx.x * 256;
    float* P = (float*)(sm + LG2_POFF);
    const float IS = 0.0009765625f;
    const int g = lane >> 2, tq = lane & 3;

    if (tid == 0) { MBAR_INIT(sb + LG2_BAR0, 256); MBAR_INIT(sb + LG2_BAR1, 256); }
    __syncthreads();
    int ph0 = 0, ph1 = 0;

    // pass 1: [hid_hi; hid_lo*1024] (M=128) x W2T_hi
    {
        const int wm = w >> 1;
        const int warpM = wm * 32, warpN = (w & 1) * 128;
        float acc[2][16][4];
#pragma unroll
        for (int i = 0; i < 2; i++)
#pragma unroll
            for (int j = 0; j < 16; j++)
#pragma unroll
                for (int q = 0; q < 4; q++) acc[i][j][q] = 0.f;

        {
            uint32_t bar = sb + LG2_BAR0;
            int myA = (tid < 128) ? 1 : 0;
            MBAR_ARRIVE_TX(bar, 128u * (1 + myA));
            bulk128(sb + LG2_BOFF(0) + tid * 144,
                    g_W2T_hi + (size_t)(n_base + tid) * 512, bar);
            if (myA)
                bulk128(sb + LG2_AOFF(0) + tid * 144, g_hid16 + tid * 512, bar);
        }
        for (int c = 0; c < 8; c++) {
            const int buf = c & 1;
            if (c + 1 < 8) {
                uint32_t bar = sb + ((buf ^ 1) ? LG2_BAR1 : LG2_BAR0);
                int myA = (tid < 128) ? 1 : 0;
                MBAR_ARRIVE_TX(bar, 128u * (1 + myA));
                bulk128(sb + LG2_BOFF(buf ^ 1) + tid * 144,
                        g_W2T_hi + (size_t)(n_base + tid) * 512 + (c + 1) * 64, bar);
                if (myA)
                    bulk128(sb + LG2_AOFF(buf ^ 1) + tid * 144,
                            g_hid16 + tid * 512 + (c + 1) * 64, bar);
            }
            if (buf == 0) { MBAR_WAIT(sb + LG2_BAR0, ph0); ph0 ^= 1; }
            else          { MBAR_WAIT(sb + LG2_BAR1, ph1); ph1 ^= 1; }
            __syncthreads();
            lg_chunk_compute<16>(sb + LG2_AOFF(buf), sb + LG2_BOFF(buf),
                                 warpM, warpN, lane, acc);
            __syncthreads();
        }
        if (wm >= 2) {
#pragma unroll
            for (int mt = 0; mt < 2; mt++) {
                int m = warpM - 64 + mt * 16 + g;
#pragma unroll
                for (int nt = 0; nt < 16; nt++) {
                    int col = warpN + nt * 8 + tq * 2;
                    P[m * LG2_PSTR + col]           = acc[mt][nt][0] * IS;
                    P[m * LG2_PSTR + col + 1]       = acc[mt][nt][1] * IS;
                    P[(m + 8) * LG2_PSTR + col]     = acc[mt][nt][2] * IS;
                    P[(m + 8) * LG2_PSTR + col + 1] = acc[mt][nt][3] * IS;
                }
            }
        }
        __syncthreads();
        if (wm < 2) {
#pragma unroll
            for (int mt = 0; mt < 2; mt++) {
                int m = warpM + mt * 16 + g;
#pragma unroll
                for (int nt = 0; nt < 16; nt++) {
                    int col = warpN + nt * 8 + tq * 2;
                    P[m * LG2_PSTR + col]           += acc[mt][nt][0];
                    P[m * LG2_PSTR + col + 1]       += acc[mt][nt][1];
                    P[(m + 8) * LG2_PSTR + col]     += acc[mt][nt][2];
                    P[(m + 8) * LG2_PSTR + col + 1] += acc[mt][nt][3];
                }
            }
        }
        __syncthreads();
    }

    // pass 2: hid_hi (M=64) x W2T_lo*1024
    {
        const int warpM = (w >> 2) * 32, warpN = (w & 3) * 64;
        float acc[2][8][4];
#pragma unroll
        for (int i = 0; i < 2; i++)
#pragma unroll
            for (int j = 0; j < 8; j++)
#pragma unroll
                for (int q = 0; q < 4; q++) acc[i][j][q] = 0.f;

        {
            uint32_t bar = sb + LG2_BAR0;
            int myA = (tid < 64) ? 1 : 0;
            MBAR_ARRIVE_TX(bar, 128u * (1 + myA));
            bulk128(sb + LG2_BOFF(0) + tid * 144,
                    g_W2T_lo + (size_t)(n_base + tid) * 512, bar);
            if (myA)
                bulk128(sb + LG2_AOFF(0) + tid * 144, g_hid16 + tid * 512, bar);
        }
        for (int c = 0; c < 8; c++) {
            const int buf = c & 1;
            if (c + 1 < 8) {
                uint32_t bar = sb + ((buf ^ 1) ? LG2_BAR1 : LG2_BAR0);
                int myA = (tid < 64) ? 1 : 0;
                MBAR_ARRIVE_TX(bar, 128u * (1 + myA));
                bulk128(sb + LG2_BOFF(buf ^ 1) + tid * 144,
                        g_W2T_lo + (size_t)(n_base + tid) * 512 + (c + 1) * 64, bar);
                if (myA)
                    bulk128(sb + LG2_AOFF(buf ^ 1) + tid * 144,
                            g_hid16 + tid * 512 + (c + 1) * 64, bar);
            }
            if (buf == 0) { MBAR_WAIT(sb + LG2_BAR0, ph0); ph0 ^= 1; }
            else          { MBAR_WAIT(sb + LG2_BAR1, ph1); ph1 ^= 1; }
            __syncthreads();
            lg_chunk_compute<8>(sb + LG2_AOFF(buf), sb + LG2_BOFF(buf),
                                warpM, warpN, lane, acc);
            __syncthreads();
        }
#pragma unroll
        for (int mt = 0; mt < 2; mt++) {
            int m = warpM + mt * 16 + g;
#pragma unroll
            for (int nt = 0; nt < 8; nt++) {
                int col = warpN + nt * 8 + tq * 2;
                P[m * LG2_PSTR + col]           += acc[mt][nt][0] * IS;
                P[m * LG2_PSTR + col + 1]       += acc[mt][nt][1] * IS;
                P[(m + 8) * LG2_PSTR + col]     += acc[mt][nt][2] * IS;
                P[(m + 8) * LG2_PSTR + col + 1] += acc[mt][nt][3] * IS;
            }
        }
        __syncthreads();
    }

    // write final logits + bias (coalesced float4)
    for (int i = tid; i < 64 * 64; i += 256) {
        int m = i >> 6;
        int c4 = (i & 63) * 4;
        float4 p = *(float4*)&P[m * LG2_PSTR + c4];
        float4 bb = *(const float4*)&b2[n_base + c4];
        p.x += bb.x; p.y += bb.y; p.z += bb.z; p.w += bb.w;
        *(float4*)&g_logits[(size_t)m * V_ + n_base + c4] = p;
    }
}

// prep: W2[k][n] fp32 -> W2T_hi/lo[n][k] fp16 (lo scaled x1024)
__global__ void conv_w2(const float* __restrict__ W2)
{
    __shared__ float tile[32][33];
    int n0 = blockIdx.x * 32, k0 = blockIdx.y * 32;
    int tx = threadIdx.x, ty = threadIdx.y;
    for (int i = ty; i < 32; i += 8)
        tile[i][tx] = W2[(size_t)(k0 + i) * V_ + n0 + tx];
    __syncthreads();
    for (int i = ty; i < 32; i += 8) {
        float wv = tile[tx][i];
        __half hi = __float2half(wv);
        __half lo = __float2half((wv - __half2float(hi)) * 1024.f);
        size_t o = (size_t)(n0 + i) * 512 + k0 + tx;
        g_W2T_hi[o] = hi;
        g_W2T_lo[o] = lo;
    }
}

// Sum split-K partials of W1, + b1, tanh -> fp16 hi/lo rows of g_hid16
__global__ void reduce_h16(const float* __restrict__ part, const float* __restrict__ bias)
{
    int idx = blockIdx.x * 256 + threadIdx.x;   // 64*512
    int m = idx >> 9, j = idx & 511;
    float s = 0.f;
#pragma unroll
    for (int z = 0; z < 32; z++) s += part[(size_t)z * B_ * H_ + idx];
    s += bias[j];
    float h = tanhf(s);
    __half hi = __float2half(h);
    g_hid16[m * 512 + j] = hi;
    g_hid16[(m + 64) * 512 + j] = __float2half((h - __half2float(hi)) * 1024.f);
}

// out[c][r] = in[r][c]
__global__ void transpose_k(const float* __restrict__ in, float* __restrict__ out,
                            int R, int C)
{
    __shared__ float tile[32][33];
    int c = blockIdx.x * 32 + threadIdx.x;
    int r0 = blockIdx.y * 32;
    for (int i = threadIdx.y; i < 32; i += 8)
        tile[i][threadIdx.x] = in[(size_t)(r0 + i) * C + c];
    __syncthreads();
    int r2 = blockIdx.y * 32 + threadIdx.x;
    int c0 = blockIdx.x * 32;
    for (int i = threadIdx.y; i < 32; i += 8)
        out[(size_t)(c0 + i) * R + r2] = tile[threadIdx.x][i];
}

__global__ void init_state(const float* __restrict__ h0)
{
    int i = blockIdx.x * blockDim.x + threadIdx.x;
    if (i < B_) g_tok[i] = 1;                  // SOS
    if (i < B_ * H_) g_h[i] = h0[i];
}

// ============ fused attention (round-7, passing) ============
__global__ void __launch_bounds__(512, 2)
attn_fused(const float* __restrict__ emb, const float* __restrict__ v_att,
           const float* __restrict__ enc)
{
    __shared__ __align__(16) float s_q[A_];
    __shared__ __align__(16) float s_v[A_];
    __shared__ float s_sc[S_];
    __shared__ float s_attn[S_];

    const int b = blockIdx.x;
    const int tid = threadIdx.x;
    const int w = tid >> 5, lane = tid & 31;

    {
        float qs = 0.f;
#pragma unroll
        for (int z = 0; z < 16; z++)
            qs += g_partA[(size_t)z * B_ * A_ + b * A_ + tid];
        s_q[tid] = qs;
        s_v[tid] = v_att[tid];
        int tok = g_tok[b];
        float ev = emb[(size_t)tok * E_ + tid];
        g_rnn_in[b * (E_ + K_) + tid] = ev;
        g_mlp_in[b * (E_ + H_ + K_) + tid] = ev;
    }
    __syncthreads();

#pragma unroll
    for (int si = 0; si < 4; si++) {
        int s = w * 4 + si;
        const float4* kp = (const float4*)(g_keys + (size_t)(s * B_ + b) * A_);
        float acc = 0.f;
#pragma unroll
        for (int a4 = lane; a4 < A_ / 4; a4 += 32) {
            float4 k4 = kp[a4];
            float4 q4 = *(const float4*)&s_q[a4 * 4];
            float4 v4 = *(const float4*)&s_v[a4 * 4];
            acc += ftanh(q4.x + k4.x) * v4.x + ftanh(q4.y + k4.y) * v4.y
                 + ftanh(q4.z + k4.z) * v4.z + ftanh(q4.w + k4.w) * v4.w;
        }
#pragma unroll
        for (int o = 16; o; o >>= 1) acc += __shfl_xor_sync(0xffffffffu, acc, o);
        if (lane == 0) s_sc[s] = acc;
    }
    __syncthreads();

    if (w == 0) {
        float a0 = s_sc[lane], a1 = s_sc[lane + 32];
        float mx = fmaxf(a0, a1);
#pragma unroll
        for (int o = 16; o; o >>= 1) mx = fmaxf(mx, __shfl_xor_sync(0xffffffffu, mx, o));
        float e0 = __expf(a0 - mx), e1 = __expf(a1 - mx);
        float ss = e0 + e1;
#pragma unroll
        for (int o = 16; o; o >>= 1) ss += __shfl_xor_sync(0xffffffffu, ss, o);
        float inv = __fdividef(1.f, ss);
        s_attn[lane] = e0 * inv;
        s_attn[lane + 32] = e1 * inv;
    }
    __syncthreads();

    {
        int k = tid;
        float acc = 0.f;
        const float* ep = enc + (size_t)b * K_ + k;
#pragma unroll 8
        for (int s2 = 0; s2 < S_; s2++)
            acc += s_attn[s2] * ep[(size_t)s2 * (B_ * K_)];
        g_rnn_in[b * (E_ + K_) + E_ + k] = acc;
        g_mlp_in[b * (E_ + H_ + K_) + E_ + H_ + k] = acc;
    }
}

// fused GRU (round-7, passing)
__global__ void gru_fused(const float* __restrict__ b_ih, const float* __restrict__ b_hh)
{
    int idx = blockIdx.x * 256 + threadIdx.x;
    int b = idx >> 9, j = idx & 511;
    float gir = 0.f, giz = 0.f, gin = 0.f, ghr = 0.f, ghz = 0.f, ghn = 0.f;
#pragma unroll
    for (int z = 0; z < 16; z++) {
        const float* pa = g_partA + (size_t)z * B_ * G3H + b * G3H;
        const float* pb = g_partB + (size_t)z * B_ * G3H + b * G3H;
        gir += pa[j]; giz += pa[j + H_]; gin += pa[j + 2 * H_];
        ghr += pb[j]; ghz += pb[j + H_]; ghn += pb[j + 2 * H_];
    }
    gir += b_ih[j]; giz += b_ih[j + H_]; gin += b_ih[j + 2 * H_];
    ghr += b_hh[j]; ghz += b_hh[j + H_]; ghn += b_hh[j + 2 * H_];
    float r  = fsigmoid(gir + ghr);
    float z_ = fsigmoid(giz + ghz);
    float n  = ftanh(gin + r * ghn);
    float h  = g_h[idx];
    float hn = (1.f - z_) * n + z_ * h;
    g_h[idx] = hn;
    g_mlp_in[b * (E_ + H_ + K_) + E_ + j] = hn;
}

// softmax stage A: per-(b, slice of 8000) max/argmax/sum-exp. grid 256 CTAs.
__global__ void __launch_bounds__(256, 4)
softmax_stats()
{
    const int b = blockIdx.x >> 2;
    const int s = blockIdx.x & 3;
    const int tid = threadIdx.x;
    const int lane = tid & 31, w = tid >> 5;
    const int v0 = s * 8000;
    const float* lg = g_logits + (size_t)b * V_;

    __shared__ float sM[8]; __shared__ int sI[8]; __shared__ float sS[8];
    __shared__ float shM;

    float bm = -1e30f; int bi = 0;
    for (int v = v0 + tid; v < v0 + 8000; v += 256) {
        float x = lg[v];
        if (x > bm) { bm = x; bi = v; }
    }
#pragma unroll
    for (int o = 16; o; o >>= 1) {
        float om = __shfl_xor_sync(0xffffffffu, bm, o);
        int   oi = __shfl_xor_sync(0xffffffffu, bi, o);
        if (om > bm || (om == bm && oi < bi)) { bm = om; bi = oi; }
    }
    if (!lane) { sM[w] = bm; sI[w] = bi; }
    __syncthreads();
    if (tid == 0) {
        float M = sM[0]; int I = sI[0];
        for (int i = 1; i < 8; i++)
            if (sM[i] > M || (sM[i] == M && sI[i] < I)) { M = sM[i]; I = sI[i]; }
        g_smax[b * 4 + s] = M;
        g_sarg[b * 4 + s] = I;
        shM = M;
    }
    __syncthreads();
    float M = shM;

    float ss = 0.f;
    for (int v = v0 + tid; v < v0 + 8000; v += 256)
        ss += __expf(lg[v] - M);
#pragma unroll
    for (int o = 16; o; o >>= 1) ss += __shfl_xor_sync(0xffffffffu, ss, o);
    if (!lane) sS[w] = ss;
    __syncthreads();
    if (tid == 0) {
        float tt = 0.f;
        for (int i = 0; i < 8; i++) tt += sS[i];
        g_ssum[b * 4 + s] = tt;
    }
}

// softmax stage B: combine 4 slice stats, write probs. grid (64, 8) CTAs.
__global__ void __launch_bounds__(256, 4)
softmax_write(float* __restrict__ out, int t, int T)
{
    const int b = blockIdx.x;
    const int sl = blockIdx.y;          // slice of 4000
    const int tid = threadIdx.x;

    // all threads compute the combined stats redundantly (ascending order,
    // strict > keeps first-index tie-break)
    float M = g_smax[b * 4]; int I = g_sarg[b * 4];
#pragma unroll
    for (int i = 1; i < 4; i++) {
        float om = g_smax[b * 4 + i];
        if (om > M) { M = om; I = g_sarg[b * 4 + i]; }
    }
    float Z = 0.f;
#pragma unroll
    for (int i = 0; i < 4; i++)
        Z += g_ssum[b * 4 + i] * __expf(g_smax[b * 4 + i] - M);
    float inv = __fdividef(1.f, Z);

    if (sl == 0 && tid == 0) g_tok[b] = I;

    const float* lg = g_logits + (size_t)b * V_ + sl * 4000;
    float* op = out + ((size_t)b * T + t) * V_ + sl * 4000;
    for (int v = tid; v < 4000; v += 256)
        op[v] = __expf(lg[v] - M) * inv;
}

// ---------------- launch ----------------
extern "C" void kernel_launch(void* const* d_in, const int* in_sizes, int n_in,
                              void* d_out, int out_size)
{
    const float* enc   = (const float*)d_in[0];
    const float* h0    = (const float*)d_in[1];
    const float* emb   = (const float*)d_in[2];
    const float* Wq    = (const float*)d_in[3];
    const float* Wk    = (const float*)d_in[4];
    const float* v_att = (const float*)d_in[5];
    const float* W_ih  = (const float*)d_in[6];
    const float* W_hh  = (const float*)d_in[7];
    const float* b_ih  = (const float*)d_in[8];
    const float* b_hh  = (const float*)d_in[9];
    const float* W1    = (const float*)d_in[10];
    const float* b1    = (const float*)d_in[11];
    const float* W2    = (const float*)d_in[12];
    const float* b2    = (const float*)d_in[13];
    float* out = (float*)d_out;
    const int T = out_size / (B_ * V_);

    float *p_keys, *p_rnn, *p_mlp, *p_h, *p_partA, *p_partB, *p_WihT, *p_WhhT;
    cudaGetSymbolAddress((void**)&p_keys,   g_keys);
    cudaGetSymbolAddress((void**)&p_rnn,    g_rnn_in);
    cudaGetSymbolAddress((void**)&p_mlp,    g_mlp_in);
    cudaGetSymbolAddress((void**)&p_h,      g_h);
    cudaGetSymbolAddress((void**)&p_partA,  g_partA);
    cudaGetSymbolAddress((void**)&p_partB,  g_partB);
    cudaGetSymbolAddress((void**)&p_WihT,   g_WihT);
    cudaGetSymbolAddress((void**)&p_WhhT,   g_WhhT);

    cudaFuncSetAttribute(logits_fused, cudaFuncAttributeMaxDynamicSharedMemorySize,
                         LG2_SMEM);

    // per-replay prep
    init_state<<<(B_ * H_ + 255) / 256, 256>>>(h0);
    transpose_k<<<dim3((E_ + K_) / 32, G3H / 32), dim3(32, 8)>>>(W_ih, p_WihT, G3H, E_ + K_);
    transpose_k<<<dim3(H_ / 32, G3H / 32), dim3(32, 8)>>>(W_hh, p_WhhT, G3H, H_);
    conv_w2<<<dim3(V_ / 32, 512 / 32), dim3(32, 8)>>>(W2);
    gemm64<<<dim3(A_ / 128, (S_ * B_) / 64, 1), 256>>>(enc, Wk, p_keys, nullptr, K_, A_, 0);

    for (int t = 0; t < T; t++) {
        // qW = h @ Wq (split-K x16 -> partA)
        gemm64<<<dim3(A_ / 128, 1, 16), 256>>>(p_h, Wq, p_partA, nullptr, H_, A_, 0);
        attn_fused<<<B_, 512>>>(emb, v_att, enc);

        // gi = rnn_in @ W_ih^T (x16) ; gh = h @ W_hh^T (x16)
        gemm64<<<dim3(G3H / 128, 1, 16), 256>>>(p_rnn, p_WihT, p_partA, nullptr, E_ + K_, G3H, 0);
        gemm64<<<dim3(G3H / 128, 1, 16), 256>>>(p_h, p_WhhT, p_partB, nullptr, H_, G3H, 0);
        gru_fused<<<B_ * H_ / 256, 256>>>(b_ih, b_hh);

        // hidden = tanh(mlp_in @ W1 + b1) -> fp16 hi/lo (split-K x32)
        gemm64<<<dim3(H_ / 128, 1, 32), 256>>>(p_mlp, W1, p_partA, nullptr, E_ + H_ + K_, H_, 0);
        reduce_h16<<<B_ * H_ / 256, 256>>>(p_partA, b1);

        // logits (hh + lh/1024 + hl/1024 + b2), single wave
        logits_fused<<<125, 256, LG2_SMEM>>>(b2);

        // softmax: 256-CTA stats + 512-CTA write
        softmax_stats<<<B_ * 4, 256>>>();
        softmax_write<<<dim3(B_, 8), 256>>>(out, t, T);
    }
}

// round 16
// speedup vs baseline: 1.1967x; 1.0207x over previous
#include <cuda_runtime.h>
#include <cuda_fp16.h>
#include <math.h>
#include <stdint.h>

#define S_  64
#define B_  64
#define K_  512
#define H_  512
#define E_  512
#define A_  512
#define V_  32000
#define G3H 1536

// ---------------- scratch (static device memory; no allocations) ----------------
__device__ float g_keys[S_ * B_ * A_];
__device__ float g_rnn_in[B_ * (E_ + K_)];
__device__ float g_mlp_in[B_ * (E_ + H_ + K_)];
__device__ float g_h[B_ * H_];
__device__ float g_logits[(size_t)B_ * V_];
__device__ float g_partA[16 * B_ * G3H];
__device__ float g_partB[16 * B_ * G3H];
__device__ float g_WihT[(E_ + K_) * G3H];
__device__ float g_WhhT[H_ * G3H];
__device__ int   g_tok[B_];
// fp16 split operands for the HMMA logits GEMM
__device__ __half g_W2T_hi[(size_t)V_ * 512];   // [n][k]
__device__ __half g_W2T_lo[(size_t)V_ * 512];   // [n][k] (x1024)
__device__ __half g_hid16[128 * 512];           // rows 0-63 hi, 64-127 lo*1024

// ---------------- fast math ----------------
__device__ __forceinline__ float ftanh(float x) {
    float t = __expf(-2.f * fabsf(x));
    float r = __fdividef(1.f - t, 1.f + t);
    return copysignf(r, x);
}
__device__ __forceinline__ float fsigmoid(float x) {
    return __fdividef(1.f, 1.f + __expf(-x));
}

// ---------------- packed f32x2 FMA ----------------
__device__ __forceinline__ float2 ffma2(float2 a, float2 b, float2 c) {
    unsigned long long ua = *reinterpret_cast<unsigned long long*>(&a);
    unsigned long long ub = *reinterpret_cast<unsigned long long*>(&b);
    unsigned long long uc = *reinterpret_cast<unsigned long long*>(&c);
    unsigned long long ud;
    asm("fma.rn.f32x2 %0, %1, %2, %3;" : "=l"(ud) : "l"(ua), "l"(ub), "l"(uc));
    return *reinterpret_cast<float2*>(&ud);
}

// ---------------- baseline-PTX async helpers ----------------
__device__ __forceinline__ uint32_t smem_to_u32(const void* p) {
    uint32_t a;
    asm("{ .reg .u64 t; cvta.to.shared.u64 t, %1; cvt.u32.u64 %0, t; }"
        : "=r"(a) : "l"(p));
    return a;
}
#define MBAR_INIT(mb, c) asm volatile("mbarrier.init.shared.b64 [%0], %1;" :: "r"(mb), "r"((uint32_t)(c)) : "memory")
#define MBAR_ARRIVE_TX(mb, tx) asm volatile("mbarrier.arrive.expect_tx.shared.b64 _, [%0], %1;" :: "r"(mb), "r"((uint32_t)(tx)) : "memory")
#define MBAR_WAIT(mb, par) do {                                              \
    uint32_t _m = (mb), _p = (par), _d;                                      \
    asm volatile("{\n\t.reg .pred p;\n\t"                                    \
        "mbarrier.try_wait.parity.acquire.cta.shared::cta.b64 p, [%1], %2;\n\t" \
        "selp.b32 %0, 1, 0, p;\n\t}" : "=r"(_d) : "r"(_m), "r"(_p) : "memory"); \
    if (!_d) {                                                               \
        asm volatile("{\n\t.reg .pred P1;\n\tWL_%=:\n\t"                     \
            "mbarrier.try_wait.parity.acquire.cta.shared::cta.b64 P1, [%0], %1, 0x989680;\n\t" \
            "@P1 bra.uni WD_%=;\n\tbra.uni WL_%=;\n\tWD_%=:\n\t}"            \
            :: "r"(_m), "r"(_p) : "memory");                                 \
    }                                                                        \
} while (0)

__device__ __forceinline__ void bulk128(uint32_t dst, const void* src, uint32_t mbar) {
    asm volatile(
        "cp.async.bulk.shared::cluster.global.mbarrier::complete_tx::bytes "
        "[%0], [%1], %2, [%3];"
        :: "r"(dst), "l"(src), "r"(128u), "r"(mbar) : "memory");
}
__device__ __forceinline__ void ldsm4(uint32_t& r0, uint32_t& r1, uint32_t& r2,
                                      uint32_t& r3, uint32_t sa) {
    asm volatile("ldmatrix.sync.aligned.m8n8.x4.shared.b16 {%0,%1,%2,%3}, [%4];"
                 : "=r"(r0), "=r"(r1), "=r"(r2), "=r"(r3) : "r"(sa));
}
__device__ __forceinline__ void mma16816(float* c, uint32_t a0, uint32_t a1,
                                         uint32_t a2, uint32_t a3,
                                         uint32_t b0, uint32_t b1) {
    asm volatile(
        "mma.sync.aligned.m16n8k16.row.col.f32.f16.f16.f32 "
        "{%0,%1,%2,%3}, {%4,%5,%6,%7}, {%8,%9}, {%0,%1,%2,%3};"
        : "+f"(c[0]), "+f"(c[1]), "+f"(c[2]), "+f"(c[3])
        : "r"(a0), "r"(a1), "r"(a2), "r"(a3), "r"(b0), "r"(b1));
}

// ============ generic NN GEMM (small): tile 64x128 (round-7, passing) ============
__device__ __forceinline__ void gemm_compute(
    const float (*As2)[130], const float (*Bs)[128],
    int m0, int bn, float2 acc[4][4])
{
#pragma unroll
    for (int kk = 0; kk < 16; kk++) {
        float2 ad[4];
#pragma unroll
        for (int i = 0; i < 4; i++)
            ad[i] = *(const float2*)&As2[kk][2 * (m0 + i)];
        float4 b0 = *(const float4*)&Bs[kk][bn];
        float4 b1 = *(const float4*)&Bs[kk][bn + 64];
        float2 bp[4];
        bp[0] = make_float2(b0.x, b0.y); bp[1] = make_float2(b0.z, b0.w);
        bp[2] = make_float2(b1.x, b1.y); bp[3] = make_float2(b1.z, b1.w);
#pragma unroll
        for (int i = 0; i < 4; i++)
#pragma unroll
            for (int j = 0; j < 4; j++)
                acc[i][j] = ffma2(ad[i], bp[j], acc[i][j]);
    }
}

__global__ void __launch_bounds__(256, 3)
gemm64(const float* __restrict__ A, const float* __restrict__ B,
       float* __restrict__ C, const float* __restrict__ bias,
       int K, int N, int act)
{
    __shared__ __align__(16) float As2[2][16][130];
    __shared__ __align__(16) float Bs[2][16][128];

    const int tid = threadIdx.x;
    const int Keff = K / gridDim.z;
    const float* Ap = A + (size_t)blockIdx.z * Keff;
    const float* Bp = B + (size_t)blockIdx.z * Keff * N;
    float* Cp = C + (size_t)blockIdx.z * 64 * N;

    const int m_base = blockIdx.y * 64;
    const int n_base = blockIdx.x * 128;

    const int ty = tid >> 4, tx = tid & 15;
    const int m0 = ty * 4;
    const int bn = tx * 4;

    const int am = tid >> 2, ak = (tid & 3) * 4;
    const int bk0 = tid >> 4;

    const float* Aload = Ap + (size_t)(m_base + am) * K + ak;
    const float* Bload = Bp + (size_t)bk0 * N + n_base + bn;

    float2 acc[4][4];
#pragma unroll
    for (int i = 0; i < 4; i++)
#pragma unroll
        for (int j = 0; j < 4; j++) acc[i][j] = make_float2(0.f, 0.f);

    float4 aR  = *(const float4*)Aload;
    float4 bR0 = *(const float4*)Bload;
    float4 bR1 = *(const float4*)(Bload + 64);

    *(float2*)&As2[0][ak + 0][2 * am] = make_float2(aR.x, aR.x);
    *(float2*)&As2[0][ak + 1][2 * am] = make_float2(aR.y, aR.y);
    *(float2*)&As2[0][ak + 2][2 * am] = make_float2(aR.z, aR.z);
    *(float2*)&As2[0][ak + 3][2 * am] = make_float2(aR.w, aR.w);
    *(float4*)&Bs[0][bk0][bn]      = bR0;
    *(float4*)&Bs[0][bk0][bn + 64] = bR1;
    __syncthreads();

    int buf = 0;
    for (int k0 = 16; k0 < Keff; k0 += 16) {
        float4 aN  = *(const float4*)(Aload + k0);
        float4 bN0 = *(const float4*)(Bload + (size_t)k0 * N);
        float4 bN1 = *(const float4*)(Bload + (size_t)k0 * N + 64);

        gemm_compute(As2[buf], Bs[buf], m0, bn, acc);

        int nb = buf ^ 1;
        *(float2*)&As2[nb][ak + 0][2 * am] = make_float2(aN.x, aN.x);
        *(float2*)&As2[nb][ak + 1][2 * am] = make_float2(aN.y, aN.y);
        *(float2*)&As2[nb][ak + 2][2 * am] = make_float2(aN.z, aN.z);
        *(float2*)&As2[nb][ak + 3][2 * am] = make_float2(aN.w, aN.w);
        *(float4*)&Bs[nb][bk0][bn]      = bN0;
        *(float4*)&Bs[nb][bk0][bn + 64] = bN1;
        __syncthreads();
        buf = nb;
    }
    gemm_compute(As2[buf], Bs[buf], m0, bn, acc);

#pragma unroll
    for (int i = 0; i < 4; i++) {
#pragma unroll
        for (int j = 0; j < 4; j++) {
            int n = n_base + bn + (j & 1) * 2 + (j >> 1) * 64;
            float2 v = acc[i][j];
            if (bias) { v.x += bias[n]; v.y += bias[n + 1]; }
            if (act)  { v.x = tanhf(v.x); v.y = tanhf(v.y); }
            *(float2*)&Cp[(size_t)(m_base + m0 + i) * N + n] = v;
        }
    }
}

// ============ merged HMMA fp16-split logits GEMM (round-7, passing) ============
#define LG2_AOFF(b) ((b) * 18432)
#define LG2_BOFF(b) (36864 + (b) * 36864)
#define LG2_POFF    110592
#define LG2_PSTR    264
#define LG2_BAR0    178176
#define LG2_BAR1    178184
#define LG2_SMEM    178208

template<int NT>
__device__ __forceinline__ void lg_chunk_compute(
    uint32_t ab, uint32_t bb, int warpM, int warpN, int lane,
    float (&acc)[2][NT][4])
{
#pragma unroll
    for (int kk = 0; kk < 4; kk++) {
        uint32_t af[2][4];
#pragma unroll
        for (int mt = 0; mt < 2; mt++) {
            int row = warpM + mt * 16 + (lane & 15);
            uint32_t sa = ab + row * 144 + kk * 32 + ((lane >> 4) << 4);
            ldsm4(af[mt][0], af[mt][1], af[mt][2], af[mt][3], sa);
        }
#pragma unroll
        for (int np = 0; np < NT / 2; np++) {
            int nr = warpN + np * 16 + (lane & 7) + (((lane >> 4) & 1) << 3);
            uint32_t sbad = bb + nr * 144 + kk * 32 + (((lane >> 3) & 1) << 4);
            uint32_t b0, b1, b2r, b3;
            ldsm4(b0, b1, b2r, b3, sbad);
            mma16816(acc[0][2 * np],     af[0][0], af[0][1], af[0][2], af[0][3], b0, b1);
            mma16816(acc[1][2 * np],     af[1][0], af[1][1], af[1][2], af[1][3], b0, b1);
            mma16816(acc[0][2 * np + 1], af[0][0], af[0][1], af[0][2], af[0][3], b2r, b3);
            mma16816(acc[1][2 * np + 1], af[1][0], af[1][1], af[1][2], af[1][3], b2r, b3);
        }
    }
}

__global__ void __launch_bounds__(256, 1)
logits_fused(const float* __restrict__ b2)
{
    extern __shared__ __align__(16) char sm[];
    const uint32_t sb = smem_to_u32(sm);
    const int tid = threadIdx.x;
    const int w = tid >> 5, lane = tid & 31;
    const int n_base = blockIdx.x * 256;
    float* P = (float*)(sm + LG2_POFF);
    const float IS = 0.0009765625f;
    const int g = lane >> 2, tq = lane & 3;

    if (tid == 0) { MBAR_INIT(sb + LG2_BAR0, 256); MBAR_INIT(sb + LG2_BAR1, 256); }
    __syncthreads();
    int ph0 = 0, ph1 = 0;

    // pass 1: [hid_hi; hid_lo*1024] (M=128) x W2T_hi
    {
        const int wm = w >> 1;
        const int warpM = wm * 32, warpN = (w & 1) * 128;
        float acc[2][16][4];
#pragma unroll
        for (int i = 0; i < 2; i++)
#pragma unroll
            for (int j = 0; j < 16; j++)
#pragma unroll
                for (int q = 0; q < 4; q++) acc[i][j][q] = 0.f;

        {
            uint32_t bar = sb + LG2_BAR0;
            int myA = (tid < 128) ? 1 : 0;
            MBAR_ARRIVE_TX(bar, 128u * (1 + myA));
            bulk128(sb + LG2_BOFF(0) + tid * 144,
                    g_W2T_hi + (size_t)(n_base + tid) * 512, bar);
            if (myA)
                bulk128(sb + LG2_AOFF(0) + tid * 144, g_hid16 + tid * 512, bar);
        }
        for (int c = 0; c < 8; c++) {
            const int buf = c & 1;
            if (c + 1 < 8) {
                uint32_t bar = sb + ((buf ^ 1) ? LG2_BAR1 : LG2_BAR0);
                int myA = (tid < 128) ? 1 : 0;
                MBAR_ARRIVE_TX(bar, 128u * (1 + myA));
                bulk128(sb + LG2_BOFF(buf ^ 1) + tid * 144,
                        g_W2T_hi + (size_t)(n_base + tid) * 512 + (c + 1) * 64, bar);
                if (myA)
                    bulk128(sb + LG2_AOFF(buf ^ 1) + tid * 144,
                            g_hid16 + tid * 512 + (c + 1) * 64, bar);
            }
            if (buf == 0) { MBAR_WAIT(sb + LG2_BAR0, ph0); ph0 ^= 1; }
            else          { MBAR_WAIT(sb + LG2_BAR1, ph1); ph1 ^= 1; }
            __syncthreads();
            lg_chunk_compute<16>(sb + LG2_AOFF(buf), sb + LG2_BOFF(buf),
                                 warpM, warpN, lane, acc);
            __syncthreads();
        }
        if (wm >= 2) {
#pragma unroll
            for (int mt = 0; mt < 2; mt++) {
                int m = warpM - 64 + mt * 16 + g;
#pragma unroll
                for (int nt = 0; nt < 16; nt++) {
                    int col = warpN + nt * 8 + tq * 2;
                    P[m * LG2_PSTR + col]           = acc[mt][nt][0] * IS;
                    P[m * LG2_PSTR + col + 1]       = acc[mt][nt][1] * IS;
                    P[(m + 8) * LG2_PSTR + col]     = acc[mt][nt][2] * IS;
                    P[(m + 8) * LG2_PSTR + col + 1] = acc[mt][nt][3] * IS;
                }
            }
        }
        __syncthreads();
        if (wm < 2) {
#pragma unroll
            for (int mt = 0; mt < 2; mt++) {
                int m = warpM + mt * 16 + g;
#pragma unroll
                for (int nt = 0; nt < 16; nt++) {
                    int col = warpN + nt * 8 + tq * 2;
                    P[m * LG2_PSTR + col]           += acc[mt][nt][0];
                    P[m * LG2_PSTR + col + 1]       += acc[mt][nt][1];
                    P[(m + 8) * LG2_PSTR + col]     += acc[mt][nt][2];
                    P[(m + 8) * LG2_PSTR + col + 1] += acc[mt][nt][3];
                }
            }
        }
        __syncthreads();
    }

    // pass 2: hid_hi (M=64) x W2T_lo*1024
    {
        const int warpM = (w >> 2) * 32, warpN = (w & 3) * 64;
        float acc[2][8][4];
#pragma unroll
        for (int i = 0; i < 2; i++)
#pragma unroll
            for (int j = 0; j < 8; j++)
#pragma unroll
                for (int q = 0; q < 4; q++) acc[i][j][q] = 0.f;

        {
            uint32_t bar = sb + LG2_BAR0;
            int myA = (tid < 64) ? 1 : 0;
            MBAR_ARRIVE_TX(bar, 128u * (1 + myA));
            bulk128(sb + LG2_BOFF(0) + tid * 144,
                    g_W2T_lo + (size_t)(n_base + tid) * 512, bar);
            if (myA)
                bulk128(sb + LG2_AOFF(0) + tid * 144, g_hid16 + tid * 512, bar);
        }
        for (int c = 0; c < 8; c++) {
            const int buf = c & 1;
            if (c + 1 < 8) {
                uint32_t bar = sb + ((buf ^ 1) ? LG2_BAR1 : LG2_BAR0);
                int myA = (tid < 64) ? 1 : 0;
                MBAR_ARRIVE_TX(bar, 128u * (1 + myA));
                bulk128(sb + LG2_BOFF(buf ^ 1) + tid * 144,
                        g_W2T_lo + (size_t)(n_base + tid) * 512 + (c + 1) * 64, bar);
                if (myA)
                    bulk128(sb + LG2_AOFF(buf ^ 1) + tid * 144,
                            g_hid16 + tid * 512 + (c + 1) * 64, bar);
            }
            if (buf == 0) { MBAR_WAIT(sb + LG2_BAR0, ph0); ph0 ^= 1; }
            else          { MBAR_WAIT(sb + LG2_BAR1, ph1); ph1 ^= 1; }
            __syncthreads();
            lg_chunk_compute<8>(sb + LG2_AOFF(buf), sb + LG2_BOFF(buf),
                                warpM, warpN, lane, acc);
            __syncthreads();
        }
#pragma unroll
        for (int mt = 0; mt < 2; mt++) {
            int m = warpM + mt * 16 + g;
#pragma unroll
            for (int nt = 0; nt < 8; nt++) {
                int col = warpN + nt * 8 + tq * 2;
                P[m * LG2_PSTR + col]           += acc[mt][nt][0] * IS;
                P[m * LG2_PSTR + col + 1]       += acc[mt][nt][1] * IS;
                P[(m + 8) * LG2_PSTR + col]     += acc[mt][nt][2] * IS;
                P[(m + 8) * LG2_PSTR + col + 1] += acc[mt][nt][3] * IS;
            }
        }
        __syncthreads();
    }

    // write final logits + bias (coalesced float4)
    for (int i = tid; i < 64 * 64; i += 256) {
        int m = i >> 6;
        int c4 = (i & 63) * 4;
        float4 p = *(float4*)&P[m * LG2_PSTR + c4];
        float4 bb = *(const float4*)&b2[n_base + c4];
        p.x += bb.x; p.y += bb.y; p.z += bb.z; p.w += bb.w;
        *(float4*)&g_logits[(size_t)m * V_ + n_base + c4] = p;
    }
}

// prep: W2[k][n] fp32 -> W2T_hi/lo[n][k] fp16, half2-coalesced writes.
// grid (1000, 8), block 256. Tile: 32 n-cols x 64 k-rows.
__global__ void conv_w2(const float* __restrict__ W2)
{
    __shared__ float T[64][33];
    const int n0 = blockIdx.x * 32;
    const int k0 = blockIdx.y * 64;
    const int tx = threadIdx.x & 31, w = threadIdx.x >> 5;

    for (int i = w; i < 64; i += 8)
        T[i][tx] = W2[(size_t)(k0 + i) * V_ + n0 + tx];
    __syncthreads();

#pragma unroll
    for (int r = 0; r < 4; r++) {
        int n = w * 4 + r;
        float a = T[2 * tx][n], b = T[2 * tx + 1][n];
        __half ha = __float2half(a), hb = __float2half(b);
        __half la = __float2half((a - __half2float(ha)) * 1024.f);
        __half lb = __float2half((b - __half2float(hb)) * 1024.f);
        size_t o = (size_t)(n0 + n) * 512 + k0 + 2 * tx;
        *(__half2*)&g_W2T_hi[o] = __halves2half2(ha, hb);
        *(__half2*)&g_W2T_lo[o] = __halves2half2(la, lb);
    }
}

// Sum split-K partials of W1, + b1, tanh -> fp16 hi/lo rows of g_hid16
__global__ void reduce_h16(const float* __restrict__ part, const float* __restrict__ bias)
{
    int idx = blockIdx.x * 256 + threadIdx.x;   // 64*512
    int m = idx >> 9, j = idx & 511;
    float s = 0.f;
#pragma unroll
    for (int z = 0; z < 32; z++) s += part[(size_t)z * B_ * H_ + idx];
    s += bias[j];
    float h = tanhf(s);
    __half hi = __float2half(h);
    g_hid16[m * 512 + j] = hi;
    g_hid16[(m + 64) * 512 + j] = __float2half((h - __half2float(hi)) * 1024.f);
}

// out[c][r] = in[r][c]
__global__ void transpose_k(const float* __restrict__ in, float* __restrict__ out,
                            int R, int C)
{
    __shared__ float tile[32][33];
    int c = blockIdx.x * 32 + threadIdx.x;
    int r0 = blockIdx.y * 32;
    for (int i = threadIdx.y; i < 32; i += 8)
        tile[i][threadIdx.x] = in[(size_t)(r0 + i) * C + c];
    __syncthreads();
    int r2 = blockIdx.y * 32 + threadIdx.x;
    int c0 = blockIdx.x * 32;
    for (int i = threadIdx.y; i < 32; i += 8)
        out[(size_t)(c0 + i) * R + r2] = tile[threadIdx.x][i];
}

__global__ void init_state(const float* __restrict__ h0)
{
    int i = blockIdx.x * blockDim.x + threadIdx.x;
    if (i < B_) g_tok[i] = 1;                  // SOS
    if (i < B_ * H_) g_h[i] = h0[i];
}

// ============ fused attention (round-7, passing) ============
__global__ void __launch_bounds__(512, 2)
attn_fused(const float* __restrict__ emb, const float* __restrict__ v_att,
           const float* __restrict__ enc)
{
    __shared__ __align__(16) float s_q[A_];
    __shared__ __align__(16) float s_v[A_];
    __shared__ float s_sc[S_];
    __shared__ float s_attn[S_];

    const int b = blockIdx.x;
    const int tid = threadIdx.x;
    const int w = tid >> 5, lane = tid & 31;

    {
        float qs = 0.f;
#pragma unroll
        for (int z = 0; z < 16; z++)
            qs += g_partA[(size_t)z * B_ * A_ + b * A_ + tid];
        s_q[tid] = qs;
        s_v[tid] = v_att[tid];
        int tok = g_tok[b];
        float ev = emb[(size_t)tok * E_ + tid];
        g_rnn_in[b * (E_ + K_) + tid] = ev;
        g_mlp_in[b * (E_ + H_ + K_) + tid] = ev;
    }
    __syncthreads();

#pragma unroll
    for (int si = 0; si < 4; si++) {
        int s = w * 4 + si;
        const float4* kp = (const float4*)(g_keys + (size_t)(s * B_ + b) * A_);
        float acc = 0.f;
#pragma unroll
        for (int a4 = lane; a4 < A_ / 4; a4 += 32) {
            float4 k4 = kp[a4];
            float4 q4 = *(const float4*)&s_q[a4 * 4];
            float4 v4 = *(const float4*)&s_v[a4 * 4];
            acc += ftanh(q4.x + k4.x) * v4.x + ftanh(q4.y + k4.y) * v4.y
                 + ftanh(q4.z + k4.z) * v4.z + ftanh(q4.w + k4.w) * v4.w;
        }
#pragma unroll
        for (int o = 16; o; o >>= 1) acc += __shfl_xor_sync(0xffffffffu, acc, o);
        if (lane == 0) s_sc[s] = acc;
    }
    __syncthreads();

    if (w == 0) {
        float a0 = s_sc[lane], a1 = s_sc[lane + 32];
        float mx = fmaxf(a0, a1);
#pragma unroll
        for (int o = 16; o; o >>= 1) mx = fmaxf(mx, __shfl_xor_sync(0xffffffffu, mx, o));
        float e0 = __expf(a0 - mx), e1 = __expf(a1 - mx);
        float ss = e0 + e1;
#pragma unroll
        for (int o = 16; o; o >>= 1) ss += __shfl_xor_sync(0xffffffffu, ss, o);
        float inv = __fdividef(1.f, ss);
        s_attn[lane] = e0 * inv;
        s_attn[lane + 32] = e1 * inv;
    }
    __syncthreads();

    {
        int k = tid;
        float acc = 0.f;
        const float* ep = enc + (size_t)b * K_ + k;
#pragma unroll 8
        for (int s2 = 0; s2 < S_; s2++)
            acc += s_attn[s2] * ep[(size_t)s2 * (B_ * K_)];
        g_rnn_in[b * (E_ + K_) + E_ + k] = acc;
        g_mlp_in[b * (E_ + H_ + K_) + E_ + H_ + k] = acc;
    }
}

// fused GRU (round-7, passing)
__global__ void gru_fused(const float* __restrict__ b_ih, const float* __restrict__ b_hh)
{
    int idx = blockIdx.x * 256 + threadIdx.x;
    int b = idx >> 9, j = idx & 511;
    float gir = 0.f, giz = 0.f, gin = 0.f, ghr = 0.f, ghz = 0.f, ghn = 0.f;
#pragma unroll
    for (int z = 0; z < 16; z++) {
        const float* pa = g_partA + (size_t)z * B_ * G3H + b * G3H;
        const float* pb = g_partB + (size_t)z * B_ * G3H + b * G3H;
        gir += pa[j]; giz += pa[j + H_]; gin += pa[j + 2 * H_];
        ghr += pb[j]; ghz += pb[j + H_]; ghn += pb[j + 2 * H_];
    }
    gir += b_ih[j]; giz += b_ih[j + H_]; gin += b_ih[j + 2 * H_];
    ghr += b_hh[j]; ghz += b_hh[j + H_]; ghn += b_hh[j + 2 * H_];
    float r  = fsigmoid(gir + ghr);
    float z_ = fsigmoid(giz + ghz);
    float n  = ftanh(gin + r * ghn);
    float h  = g_h[idx];
    float hn = (1.f - z_) * n + z_ * h;
    g_h[idx] = hn;
    g_mlp_in[b * (E_ + H_ + K_) + E_ + j] = hn;
}

// softmax over vocab from final logits (round-7, passing)
__global__ void softmax_v(float* __restrict__ out, int t, int T)
{
    int b = blockIdx.x;
    int tid = threadIdx.x;
    const float* lg = g_logits + (size_t)b * V_;
    float* op = out + ((size_t)b * T + t) * V_;
    int lane = tid & 31, w = tid >> 5;

    float bm = -1e30f; int bi = 0;
    for (int v = tid; v < V_; v += 512) {
        float x = lg[v];
        if (x > bm) { bm = x; bi = v; }
    }
    __shared__ float smax[16]; __shared__ int sidx[16]; __shared__ float ssum[16];
#pragma unroll
    for (int o = 16; o; o >>= 1) {
        float om = __shfl_xor_sync(0xffffffffu, bm, o);
        int   oi = __shfl_xor_sync(0xffffffffu, bi, o);
        if (om > bm || (om == bm && oi < bi)) { bm = om; bi = oi; }
    }
    if (!lane) { smax[w] = bm; sidx[w] = bi; }
    __syncthreads();
    if (tid == 0) {
        float M = smax[0]; int I = sidx[0];
        for (int i = 1; i < 16; i++)
            if (smax[i] > M || (smax[i] == M && sidx[i] < I)) { M = smax[i]; I = sidx[i]; }
        smax[0] = M;
        g_tok[b] = I;
    }
    __syncthreads();
    float mx = smax[0];

    float s = 0.f;
    for (int v = tid; v < V_; v += 512) s += __expf(lg[v] - mx);
#pragma unroll
    for (int o = 16; o; o >>= 1) s += __shfl_xor_sync(0xffffffffu, s, o);
    if (!lane) ssum[w] = s;
    __syncthreads();
    if (tid == 0) {
        float tt = 0.f;
        for (int i = 0; i < 16; i++) tt += ssum[i];
        ssum[0] = tt;
    }
    __syncthreads();
    float inv = __fdividef(1.f, ssum[0]);
    for (int v = tid; v < V_; v += 512) op[v] = __expf(lg[v] - mx) * inv;
}

// ---------------- launch ----------------
extern "C" void kernel_launch(void* const* d_in, const int* in_sizes, int n_in,
                              void* d_out, int out_size)
{
    const float* enc   = (const float*)d_in[0];
    const float* h0    = (const float*)d_in[1];
    const float* emb   = (const float*)d_in[2];
    const float* Wq    = (const float*)d_in[3];
    const float* Wk    = (const float*)d_in[4];
    const float* v_att = (const float*)d_in[5];
    const float* W_ih  = (const float*)d_in[6];
    const float* W_hh  = (const float*)d_in[7];
    const float* b_ih  = (const float*)d_in[8];
    const float* b_hh  = (const float*)d_in[9];
    const float* W1    = (const float*)d_in[10];
    const float* b1    = (const float*)d_in[11];
    const float* W2    = (const float*)d_in[12];
    const float* b2    = (const float*)d_in[13];
    float* out = (float*)d_out;
    const int T = out_size / (B_ * V_);

    float *p_keys, *p_rnn, *p_mlp, *p_h, *p_partA, *p_partB, *p_WihT, *p_WhhT;
    cudaGetSymbolAddress((void**)&p_keys,   g_keys);
    cudaGetSymbolAddress((void**)&p_rnn,    g_rnn_in);
    cudaGetSymbolAddress((void**)&p_mlp,    g_mlp_in);
    cudaGetSymbolAddress((void**)&p_h,      g_h);
    cudaGetSymbolAddress((void**)&p_partA,  g_partA);
    cudaGetSymbolAddress((void**)&p_partB,  g_partB);
    cudaGetSymbolAddress((void**)&p_WihT,   g_WihT);
    cudaGetSymbolAddress((void**)&p_WhhT,   g_WhhT);

    cudaFuncSetAttribute(logits_fused, cudaFuncAttributeMaxDynamicSharedMemorySize,
                         LG2_SMEM);

    // per-replay prep
    init_state<<<(B_ * H_ + 255) / 256, 256>>>(h0);
    transpose_k<<<dim3((E_ + K_) / 32, G3H / 32), dim3(32, 8)>>>(W_ih, p_WihT, G3H, E_ + K_);
    transpose_k<<<dim3(H_ / 32, G3H / 32), dim3(32, 8)>>>(W_hh, p_WhhT, G3H, H_);
    conv_w2<<<dim3(V_ / 32, 8), 256>>>(W2);
    gemm64<<<dim3(A_ / 128, (S_ * B_) / 64, 1), 256>>>(enc, Wk, p_keys, nullptr, K_, A_, 0);

    for (int t = 0; t < T; t++) {
        // qW = h @ Wq (split-K x16 -> partA)
        gemm64<<<dim3(A_ / 128, 1, 16), 256>>>(p_h, Wq, p_partA, nullptr, H_, A_, 0);
        attn_fused<<<B_, 512>>>(emb, v_att, enc);

        // gi = rnn_in @ W_ih^T (x16) ; gh = h @ W_hh^T (x16)
        gemm64<<<dim3(G3H / 128, 1, 16), 256>>>(p_rnn, p_WihT, p_partA, nullptr, E_ + K_, G3H, 0);
        gemm64<<<dim3(G3H / 128, 1, 16), 256>>>(p_h, p_WhhT, p_partB, nullptr, H_, G3H, 0);
        gru_fused<<<B_ * H_ / 256, 256>>>(b_ih, b_hh);

        // hidden = tanh(mlp_in @ W1 + b1) -> fp16 hi/lo (split-K x32)
        gemm64<<<dim3(H_ / 128, 1, 32), 256>>>(p_mlp, W1, p_partA, nullptr, E_ + H_ + K_, H_, 0);
        reduce_h16<<<B_ * H_ / 256, 256>>>(p_partA, b1);

        // logits (hh + lh/1024 + hl/1024 + b2), single wave
        logits_fused<<<125, 256, LG2_SMEM>>>(b2);

        softmax_v<<<B_, 512>>>(out, t, T);
    }
}

// round 17
// speedup vs baseline: 1.2223x; 1.0214x over previous
#include <cuda_runtime.h>
#include <cuda_fp16.h>
#include <math.h>
#include <stdint.h>

#define S_  64
#define B_  64
#define K_  512
#define H_  512
#define E_  512
#define A_  512
#define V_  32000
#define G3H 1536

// ---------------- scratch (static device memory; no allocations) ----------------
__device__ float g_keys[S_ * B_ * A_];
__device__ float g_rnn_in[B_ * (E_ + K_)];
__device__ float g_mlp_in[B_ * (E_ + H_ + K_)];
__device__ float g_h[B_ * H_];
__device__ float g_logits[(size_t)B_ * V_];
__device__ float g_partA[16 * B_ * G3H];
__device__ float g_partB[16 * B_ * G3H];
__device__ float g_WihT[(E_ + K_) * G3H];
__device__ float g_WhhT[H_ * G3H];
__device__ int   g_tok[B_];
// fp16 split operands for the HMMA logits GEMM
__device__ __half g_W2T_hi[(size_t)V_ * 512];   // [n][k]
__device__ __half g_W2T_lo[(size_t)V_ * 512];   // [n][k] (x1024)
__device__ __half g_hid16[128 * 512];           // rows 0-63 hi, 64-127 lo*1024

// ---------------- fast math ----------------
__device__ __forceinline__ float ftanh(float x) {
    float t = __expf(-2.f * fabsf(x));
    float r = __fdividef(1.f - t, 1.f + t);
    return copysignf(r, x);
}
__device__ __forceinline__ float fsigmoid(float x) {
    return __fdividef(1.f, 1.f + __expf(-x));
}

// ---------------- packed f32x2 FMA ----------------
__device__ __forceinline__ float2 ffma2(float2 a, float2 b, float2 c) {
    unsigned long long ua = *reinterpret_cast<unsigned long long*>(&a);
    unsigned long long ub = *reinterpret_cast<unsigned long long*>(&b);
    unsigned long long uc = *reinterpret_cast<unsigned long long*>(&c);
    unsigned long long ud;
    asm("fma.rn.f32x2 %0, %1, %2, %3;" : "=l"(ud) : "l"(ua), "l"(ub), "l"(uc));
    return *reinterpret_cast<float2*>(&ud);
}

// ---------------- baseline-PTX async helpers ----------------
__device__ __forceinline__ uint32_t smem_to_u32(const void* p) {
    uint32_t a;
    asm("{ .reg .u64 t; cvta.to.shared.u64 t, %1; cvt.u32.u64 %0, t; }"
        : "=r"(a) : "l"(p));
    return a;
}
#define MBAR_INIT(mb, c) asm volatile("mbarrier.init.shared.b64 [%0], %1;" :: "r"(mb), "r"((uint32_t)(c)) : "memory")
#define MBAR_ARRIVE_TX(mb, tx) asm volatile("mbarrier.arrive.expect_tx.shared.b64 _, [%0], %1;" :: "r"(mb), "r"((uint32_t)(tx)) : "memory")
#define MBAR_WAIT(mb, par) do {                                              \
    uint32_t _m = (mb), _p = (par), _d;                                      \
    asm volatile("{\n\t.reg .pred p;\n\t"                                    \
        "mbarrier.try_wait.parity.acquire.cta.shared::cta.b64 p, [%1], %2;\n\t" \
        "selp.b32 %0, 1, 0, p;\n\t}" : "=r"(_d) : "r"(_m), "r"(_p) : "memory"); \
    if (!_d) {                                                               \
        asm volatile("{\n\t.reg .pred P1;\n\tWL_%=:\n\t"                     \
            "mbarrier.try_wait.parity.acquire.cta.shared::cta.b64 P1, [%0], %1, 0x989680;\n\t" \
            "@P1 bra.uni WD_%=;\n\tbra.uni WL_%=;\n\tWD_%=:\n\t}"            \
            :: "r"(_m), "r"(_p) : "memory");                                 \
    }                                                                        \
} while (0)

__device__ __forceinline__ void bulk128(uint32_t dst, const void* src, uint32_t mbar) {
    asm volatile(
        "cp.async.bulk.shared::cluster.global.mbarrier::complete_tx::bytes "
        "[%0], [%1], %2, [%3];"
        :: "r"(dst), "l"(src), "r"(128u), "r"(mbar) : "memory");
}
__device__ __forceinline__ void ldsm4(uint32_t& r0, uint32_t& r1, uint32_t& r2,
                                      uint32_t& r3, uint32_t sa) {
    asm volatile("ldmatrix.sync.aligned.m8n8.x4.shared.b16 {%0,%1,%2,%3}, [%4];"
                 : "=r"(r0), "=r"(r1), "=r"(r2), "=r"(r3) : "r"(sa));
}
__device__ __forceinline__ void mma16816(float* c, uint32_t a0, uint32_t a1,
                                         uint32_t a2, uint32_t a3,
                                         uint32_t b0, uint32_t b1) {
    asm volatile(
        "mma.sync.aligned.m16n8k16.row.col.f32.f16.f16.f32 "
        "{%0,%1,%2,%3}, {%4,%5,%6,%7}, {%8,%9}, {%0,%1,%2,%3};"
        : "+f"(c[0]), "+f"(c[1]), "+f"(c[2]), "+f"(c[3])
        : "r"(a0), "r"(a1), "r"(a2), "r"(a3), "r"(b0), "r"(b1));
}

// ============ shared fp32 GEMM body (verified round-7 kernel) ============
__device__ __forceinline__ void gemm_compute(
    const float (*As2)[130], const float (*Bs)[128],
    int m0, int bn, float2 acc[4][4])
{
#pragma unroll
    for (int kk = 0; kk < 16; kk++) {
        float2 ad[4];
#pragma unroll
        for (int i = 0; i < 4; i++)
            ad[i] = *(const float2*)&As2[kk][2 * (m0 + i)];
        float4 b0 = *(const float4*)&Bs[kk][bn];
        float4 b1 = *(const float4*)&Bs[kk][bn + 64];
        float2 bp[4];
        bp[0] = make_float2(b0.x, b0.y); bp[1] = make_float2(b0.z, b0.w);
        bp[2] = make_float2(b1.x, b1.y); bp[3] = make_float2(b1.z, b1.w);
#pragma unroll
        for (int i = 0; i < 4; i++)
#pragma unroll
            for (int j = 0; j < 4; j++)
                acc[i][j] = ffma2(ad[i], bp[j], acc[i][j]);
    }
}

// full-body worker: C partial(z) = A[64,K_eff slice] @ B-slice, tile m_base x n_base
__device__ __forceinline__ void gemm_body(
    const float* __restrict__ A, const float* __restrict__ B,
    float* __restrict__ C, const float* __restrict__ bias,
    int K, int N, int act, int Keff, int zidx, int m_base, int n_base)
{
    __shared__ __align__(16) float As2[2][16][130];
    __shared__ __align__(16) float Bs[2][16][128];

    const int tid = threadIdx.x;
    const float* Ap = A + (size_t)zidx * Keff;
    const float* Bp = B + (size_t)zidx * Keff * N;
    float* Cp = C + (size_t)zidx * 64 * N;

    const int ty = tid >> 4, tx = tid & 15;
    const int m0 = ty * 4;
    const int bn = tx * 4;

    const int am = tid >> 2, ak = (tid & 3) * 4;
    const int bk0 = tid >> 4;

    const float* Aload = Ap + (size_t)(m_base + am) * K + ak;
    const float* Bload = Bp + (size_t)bk0 * N + n_base + bn;

    float2 acc[4][4];
#pragma unroll
    for (int i = 0; i < 4; i++)
#pragma unroll
        for (int j = 0; j < 4; j++) acc[i][j] = make_float2(0.f, 0.f);

    float4 aR  = *(const float4*)Aload;
    float4 bR0 = *(const float4*)Bload;
    float4 bR1 = *(const float4*)(Bload + 64);

    *(float2*)&As2[0][ak + 0][2 * am] = make_float2(aR.x, aR.x);
    *(float2*)&As2[0][ak + 1][2 * am] = make_float2(aR.y, aR.y);
    *(float2*)&As2[0][ak + 2][2 * am] = make_float2(aR.z, aR.z);
    *(float2*)&As2[0][ak + 3][2 * am] = make_float2(aR.w, aR.w);
    *(float4*)&Bs[0][bk0][bn]      = bR0;
    *(float4*)&Bs[0][bk0][bn + 64] = bR1;
    __syncthreads();

    int buf = 0;
    for (int k0 = 16; k0 < Keff; k0 += 16) {
        float4 aN  = *(const float4*)(Aload + k0);
        float4 bN0 = *(const float4*)(Bload + (size_t)k0 * N);
        float4 bN1 = *(const float4*)(Bload + (size_t)k0 * N + 64);

        gemm_compute(As2[buf], Bs[buf], m0, bn, acc);

        int nb = buf ^ 1;
        *(float2*)&As2[nb][ak + 0][2 * am] = make_float2(aN.x, aN.x);
        *(float2*)&As2[nb][ak + 1][2 * am] = make_float2(aN.y, aN.y);
        *(float2*)&As2[nb][ak + 2][2 * am] = make_float2(aN.z, aN.z);
        *(float2*)&As2[nb][ak + 3][2 * am] = make_float2(aN.w, aN.w);
        *(float4*)&Bs[nb][bk0][bn]      = bN0;
        *(float4*)&Bs[nb][bk0][bn + 64] = bN1;
        __syncthreads();
        buf = nb;
    }
    gemm_compute(As2[buf], Bs[buf], m0, bn, acc);

#pragma unroll
    for (int i = 0; i < 4; i++) {
#pragma unroll
        for (int j = 0; j < 4; j++) {
            int n = n_base + bn + (j & 1) * 2 + (j >> 1) * 64;
            float2 v = acc[i][j];
            if (bias) { v.x += bias[n]; v.y += bias[n + 1]; }
            if (act)  { v.x = tanhf(v.x); v.y = tanhf(v.y); }
            *(float2*)&Cp[(size_t)(m_base + m0 + i) * N + n] = v;
        }
    }
}

__global__ void __launch_bounds__(256, 3)
gemm64(const float* __restrict__ A, const float* __restrict__ B,
       float* __restrict__ C, const float* __restrict__ bias,
       int K, int N, int act)
{
    gemm_body(A, B, C, bias, K, N, act, K / gridDim.z, blockIdx.z,
              blockIdx.y * 64, blockIdx.x * 128);
}

// dual: blockIdx.y == 0 -> problem 1 (gi), == 1 -> problem 2 (gh). Same N, same z.
__global__ void __launch_bounds__(256, 3)
gemm64_dual(const float* __restrict__ A1, const float* __restrict__ B1,
            float* __restrict__ C1, int K1,
            const float* __restrict__ A2, const float* __restrict__ B2,
            float* __restrict__ C2, int K2, int N)
{
    if (blockIdx.y == 0)
        gemm_body(A1, B1, C1, nullptr, K1, N, 0, K1 / gridDim.z, blockIdx.z,
                  0, blockIdx.x * 128);
    else
        gemm_body(A2, B2, C2, nullptr, K2, N, 0, K2 / gridDim.z, blockIdx.z,
                  0, blockIdx.x * 128);
}

// ============ merged HMMA fp16-split logits GEMM (round-7, passing) ============
#define LG2_AOFF(b) ((b) * 18432)
#define LG2_BOFF(b) (36864 + (b) * 36864)
#define LG2_POFF    110592
#define LG2_PSTR    264
#define LG2_BAR0    178176
#define LG2_BAR1    178184
#define LG2_SMEM    178208

template<int NT>
__device__ __forceinline__ void lg_chunk_compute(
    uint32_t ab, uint32_t bb, int warpM, int warpN, int lane,
    float (&acc)[2][NT][4])
{
#pragma unroll
    for (int kk = 0; kk < 4; kk++) {
        uint32_t af[2][4];
#pragma unroll
        for (int mt = 0; mt < 2; mt++) {
            int row = warpM + mt * 16 + (lane & 15);
            uint32_t sa = ab + row * 144 + kk * 32 + ((lane >> 4) << 4);
            ldsm4(af[mt][0], af[mt][1], af[mt][2], af[mt][3], sa);
        }
#pragma unroll
        for (int np = 0; np < NT / 2; np++) {
            int nr = warpN + np * 16 + (lane & 7) + (((lane >> 4) & 1) << 3);
            uint32_t sbad = bb + nr * 144 + kk * 32 + (((lane >> 3) & 1) << 4);
            uint32_t b0, b1, b2r, b3;
            ldsm4(b0, b1, b2r, b3, sbad);
            mma16816(acc[0][2 * np],     af[0][0], af[0][1], af[0][2], af[0][3], b0, b1);
            mma16816(acc[1][2 * np],     af[1][0], af[1][1], af[1][2], af[1][3], b0, b1);
            mma16816(acc[0][2 * np + 1], af[0][0], af[0][1], af[0][2], af[0][3], b2r, b3);
            mma16816(acc[1][2 * np + 1], af[1][0], af[1][1], af[1][2], af[1][3], b2r, b3);
        }
    }
}

__global__ void __launch_bounds__(256, 1)
logits_fused(const float* __restrict__ b2)
{
    extern __shared__ __align__(16) char sm[];
    const uint32_t sb = smem_to_u32(sm);
    const int tid = threadIdx.x;
    const int w = tid >> 5, lane = tid & 31;
    const int n_base = blockIdx.x * 256;
    float* P = (float*)(sm + LG2_POFF);
    const float IS = 0.0009765625f;
    const int g = lane >> 2, tq = lane & 3;

    if (tid == 0) { MBAR_INIT(sb + LG2_BAR0, 256); MBAR_INIT(sb + LG2_BAR1, 256); }
    __syncthreads();
    int ph0 = 0, ph1 = 0;

    // pass 1: [hid_hi; hid_lo*1024] (M=128) x W2T_hi
    {
        const int wm = w >> 1;
        const int warpM = wm * 32, warpN = (w & 1) * 128;
        float acc[2][16][4];
#pragma unroll
        for (int i = 0; i < 2; i++)
#pragma unroll
            for (int j = 0; j < 16; j++)
#pragma unroll
                for (int q = 0; q < 4; q++) acc[i][j][q] = 0.f;

        {
            uint32_t bar = sb + LG2_BAR0;
            int myA = (tid < 128) ? 1 : 0;
            MBAR_ARRIVE_TX(bar, 128u * (1 + myA));
            bulk128(sb + LG2_BOFF(0) + tid * 144,
                    g_W2T_hi + (size_t)(n_base + tid) * 512, bar);
            if (myA)
                bulk128(sb + LG2_AOFF(0) + tid * 144, g_hid16 + tid * 512, bar);
        }
        for (int c = 0; c < 8; c++) {
            const int buf = c & 1;
            if (c + 1 < 8) {
                uint32_t bar = sb + ((buf ^ 1) ? LG2_BAR1 : LG2_BAR0);
                int myA = (tid < 128) ? 1 : 0;
                MBAR_ARRIVE_TX(bar, 128u * (1 + myA));
                bulk128(sb + LG2_BOFF(buf ^ 1) + tid * 144,
                        g_W2T_hi + (size_t)(n_base + tid) * 512 + (c + 1) * 64, bar);
                if (myA)
                    bulk128(sb + LG2_AOFF(buf ^ 1) + tid * 144,
                            g_hid16 + tid * 512 + (c + 1) * 64, bar);
            }
            if (buf == 0) { MBAR_WAIT(sb + LG2_BAR0, ph0); ph0 ^= 1; }
            else          { MBAR_WAIT(sb + LG2_BAR1, ph1); ph1 ^= 1; }
            __syncthreads();
            lg_chunk_compute<16>(sb + LG2_AOFF(buf), sb + LG2_BOFF(buf),
                                 warpM, warpN, lane, acc);
            __syncthreads();
        }
        if (wm >= 2) {
#pragma unroll
            for (int mt = 0; mt < 2; mt++) {
                int m = warpM - 64 + mt * 16 + g;
#pragma unroll
                for (int nt = 0; nt < 16; nt++) {
                    int col = warpN + nt * 8 + tq * 2;
                    P[m * LG2_PSTR + col]           = acc[mt][nt][0] * IS;
                    P[m * LG2_PSTR + col + 1]       = acc[mt][nt][1] * IS;
                    P[(m + 8) * LG2_PSTR + col]     = acc[mt][nt][2] * IS;
                    P[(m + 8) * LG2_PSTR + col + 1] = acc[mt][nt][3] * IS;
                }
            }
        }
        __syncthreads();
        if (wm < 2) {
#pragma unroll
            for (int mt = 0; mt < 2; mt++) {
                int m = warpM + mt * 16 + g;
#pragma unroll
                for (int nt = 0; nt < 16; nt++) {
                    int col = warpN + nt * 8 + tq * 2;
                    P[m * LG2_PSTR + col]           += acc[mt][nt][0];
                    P[m * LG2_PSTR + col + 1]       += acc[mt][nt][1];
                    P[(m + 8) * LG2_PSTR + col]     += acc[mt][nt][2];
                    P[(m + 8) * LG2_PSTR + col + 1] += acc[mt][nt][3];
                }
            }
        }
        __syncthreads();
    }

    // pass 2: hid_hi (M=64) x W2T_lo*1024
    {
        const int warpM = (w >> 2) * 32, warpN = (w & 3) * 64;
        float acc[2][8][4];
#pragma unroll
        for (int i = 0; i < 2; i++)
#pragma unroll
            for (int j = 0; j < 8; j++)
#pragma unroll
                for (int q = 0; q < 4; q++) acc[i][j][q] = 0.f;

        {
            uint32_t bar = sb + LG2_BAR0;
            int myA = (tid < 64) ? 1 : 0;
            MBAR_ARRIVE_TX(bar, 128u * (1 + myA));
            bulk128(sb + LG2_BOFF(0) + tid * 144,
                    g_W2T_lo + (size_t)(n_base + tid) * 512, bar);
            if (myA)
                bulk128(sb + LG2_AOFF(0) + tid * 144, g_hid16 + tid * 512, bar);
        }
        for (int c = 0; c < 8; c++) {
            const int buf = c & 1;
            if (c + 1 < 8) {
                uint32_t bar = sb + ((buf ^ 1) ? LG2_BAR1 : LG2_BAR0);
                int myA = (tid < 64) ? 1 : 0;
                MBAR_ARRIVE_TX(bar, 128u * (1 + myA));
                bulk128(sb + LG2_BOFF(buf ^ 1) + tid * 144,
                        g_W2T_lo + (size_t)(n_base + tid) * 512 + (c + 1) * 64, bar);
                if (myA)
                    bulk128(sb + LG2_AOFF(buf ^ 1) + tid * 144,
                            g_hid16 + tid * 512 + (c + 1) * 64, bar);
            }
            if (buf == 0) { MBAR_WAIT(sb + LG2_BAR0, ph0); ph0 ^= 1; }
            else          { MBAR_WAIT(sb + LG2_BAR1, ph1); ph1 ^= 1; }
            __syncthreads();
            lg_chunk_compute<8>(sb + LG2_AOFF(buf), sb + LG2_BOFF(buf),
                                warpM, warpN, lane, acc);
            __syncthreads();
        }
#pragma unroll
        for (int mt = 0; mt < 2; mt++) {
            int m = warpM + mt * 16 + g;
#pragma unroll
            for (int nt = 0; nt < 8; nt++) {
                int col = warpN + nt * 8 + tq * 2;
                P[m * LG2_PSTR + col]           += acc[mt][nt][0] * IS;
                P[m * LG2_PSTR + col + 1]       += acc[mt][nt][1] * IS;
                P[(m + 8) * LG2_PSTR + col]     += acc[mt][nt][2] * IS;
                P[(m + 8) * LG2_PSTR + col + 1] += acc[mt][nt][3] * IS;
            }
        }
        __syncthreads();
    }

    // write final logits + bias (coalesced float4)
    for (int i = tid; i < 64 * 64; i += 256) {
        int m = i >> 6;
        int c4 = (i & 63) * 4;
        float4 p = *(float4*)&P[m * LG2_PSTR + c4];
        float4 bb = *(const float4*)&b2[n_base + c4];
        p.x += bb.x; p.y += bb.y; p.z += bb.z; p.w += bb.w;
        *(float4*)&g_logits[(size_t)m * V_ + n_base + c4] = p;
    }
}

// prep: W2[k][n] fp32 -> W2T_hi/lo[n][k] fp16, half2-coalesced writes.
__global__ void conv_w2(const float* __restrict__ W2)
{
    __shared__ float T[64][33];
    const int n0 = blockIdx.x * 32;
    const int k0 = blockIdx.y * 64;
    const int tx = threadIdx.x & 31, w = threadIdx.x >> 5;

    for (int i = w; i < 64; i += 8)
        T[i][tx] = W2[(size_t)(k0 + i) * V_ + n0 + tx];
    __syncthreads();

#pragma unroll
    for (int r = 0; r < 4; r++) {
        int n = w * 4 + r;
        float a = T[2 * tx][n], b = T[2 * tx + 1][n];
        __half ha = __float2half(a), hb = __float2half(b);
        __half la = __float2half((a - __half2float(ha)) * 1024.f);
        __half lb = __float2half((b - __half2float(hb)) * 1024.f);
        size_t o = (size_t)(n0 + n) * 512 + k0 + 2 * tx;
        *(__half2*)&g_W2T_hi[o] = __halves2half2(ha, hb);
        *(__half2*)&g_W2T_lo[o] = __halves2half2(la, lb);
    }
}

// Sum split-K partials of W1, + b1, tanh -> fp16 hi/lo rows of g_hid16
__global__ void reduce_h16(const float* __restrict__ part, const float* __restrict__ bias)
{
    int idx = blockIdx.x * 256 + threadIdx.x;   // 64*512
    int m = idx >> 9, j = idx & 511;
    float s = 0.f;
#pragma unroll
    for (int z = 0; z < 32; z++) s += part[(size_t)z * B_ * H_ + idx];
    s += bias[j];
    float h = tanhf(s);
    __half hi = __float2half(h);
    g_hid16[m * 512 + j] = hi;
    g_hid16[(m + 64) * 512 + j] = __float2half((h - __half2float(hi)) * 1024.f);
}

// out[c][r] = in[r][c]
__global__ void transpose_k(const float* __restrict__ in, float* __restrict__ out,
                            int R, int C)
{
    __shared__ float tile[32][33];
    int c = blockIdx.x * 32 + threadIdx.x;
    int r0 = blockIdx.y * 32;
    for (int i = threadIdx.y; i < 32; i += 8)
        tile[i][threadIdx.x] = in[(size_t)(r0 + i) * C + c];
    __syncthreads();
    int r2 = blockIdx.y * 32 + threadIdx.x;
    int c0 = blockIdx.x * 32;
    for (int i = threadIdx.y; i < 32; i += 8)
        out[(size_t)(c0 + i) * R + r2] = tile[threadIdx.x][i];
}

__global__ void init_state(const float* __restrict__ h0)
{
    int i = blockIdx.x * blockDim.x + threadIdx.x;
    if (i < B_) g_tok[i] = 1;                  // SOS
    if (i < B_ * H_) g_h[i] = h0[i];
}

// ============ fused attention (round-7, passing) ============
__global__ void __launch_bounds__(512, 2)
attn_fused(const float* __restrict__ emb, const float* __restrict__ v_att,
           const float* __restrict__ enc)
{
    __shared__ __align__(16) float s_q[A_];
    __shared__ __align__(16) float s_v[A_];
    __shared__ float s_sc[S_];
    __shared__ float s_attn[S_];

    const int b = blockIdx.x;
    const int tid = threadIdx.x;
    const int w = tid >> 5, lane = tid & 31;

    {
        float qs = 0.f;
#pragma unroll
        for (int z = 0; z < 16; z++)
            qs += g_partA[(size_t)z * B_ * A_ + b * A_ + tid];
        s_q[tid] = qs;
        s_v[tid] = v_att[tid];
        int tok = g_tok[b];
        float ev = emb[(size_t)tok * E_ + tid];
        g_rnn_in[b * (E_ + K_) + tid] = ev;
        g_mlp_in[b * (E_ + H_ + K_) + tid] = ev;
    }
    __syncthreads();

#pragma unroll
    for (int si = 0; si < 4; si++) {
        int s = w * 4 + si;
        const float4* kp = (const float4*)(g_keys + (size_t)(s * B_ + b) * A_);
        float acc = 0.f;
#pragma unroll
        for (int a4 = lane; a4 < A_ / 4; a4 += 32) {
            float4 k4 = kp[a4];
            float4 q4 = *(const float4*)&s_q[a4 * 4];
            float4 v4 = *(const float4*)&s_v[a4 * 4];
            acc += ftanh(q4.x + k4.x) * v4.x + ftanh(q4.y + k4.y) * v4.y
                 + ftanh(q4.z + k4.z) * v4.z + ftanh(q4.w + k4.w) * v4.w;
        }
#pragma unroll
        for (int o = 16; o; o >>= 1) acc += __shfl_xor_sync(0xffffffffu, acc, o);
        if (lane == 0) s_sc[s] = acc;
    }
    __syncthreads();

    if (w == 0) {
        float a0 = s_sc[lane], a1 = s_sc[lane + 32];
        float mx = fmaxf(a0, a1);
#pragma unroll
        for (int o = 16; o; o >>= 1) mx = fmaxf(mx, __shfl_xor_sync(0xffffffffu, mx, o));
        float e0 = __expf(a0 - mx), e1 = __expf(a1 - mx);
        float ss = e0 + e1;
#pragma unroll
        for (int o = 16; o; o >>= 1) ss += __shfl_xor_sync(0xffffffffu, ss, o);
        float inv = __fdividef(1.f, ss);
        s_attn[lane] = e0 * inv;
        s_attn[lane + 32] = e1 * inv;
    }
    __syncthreads();

    {
        int k = tid;
        float acc = 0.f;
        const float* ep = enc + (size_t)b * K_ + k;
#pragma unroll 8
        for (int s2 = 0; s2 < S_; s2++)
            acc += s_attn[s2] * ep[(size_t)s2 * (B_ * K_)];
        g_rnn_in[b * (E_ + K_) + E_ + k] = acc;
        g_mlp_in[b * (E_ + H_ + K_) + E_ + H_ + k] = acc;
    }
}

// fused GRU (round-7, passing)
__global__ void gru_fused(const float* __restrict__ b_ih, const float* __restrict__ b_hh)
{
    int idx = blockIdx.x * 256 + threadIdx.x;
    int b = idx >> 9, j = idx & 511;
    float gir = 0.f, giz = 0.f, gin = 0.f, ghr = 0.f, ghz = 0.f, ghn = 0.f;
#pragma unroll
    for (int z = 0; z < 16; z++) {
        const float* pa = g_partA + (size_t)z * B_ * G3H + b * G3H;
        const float* pb = g_partB + (size_t)z * B_ * G3H + b * G3H;
        gir += pa[j]; giz += pa[j + H_]; gin += pa[j + 2 * H_];
        ghr += pb[j]; ghz += pb[j + H_]; ghn += pb[j + 2 * H_];
    }
    gir += b_ih[j]; giz += b_ih[j + H_]; gin += b_ih[j + 2 * H_];
    ghr += b_hh[j]; ghz += b_hh[j + H_]; ghn += b_hh[j + 2 * H_];
    float r  = fsigmoid(gir + ghr);
    float z_ = fsigmoid(giz + ghz);
    float n  = ftanh(gin + r * ghn);
    float h  = g_h[idx];
    float hn = (1.f - z_) * n + z_ * h;
    g_h[idx] = hn;
    g_mlp_in[b * (E_ + H_ + K_) + E_ + j] = hn;
}

// softmax over vocab from final logits (round-7, passing)
__global__ void softmax_v(float* __restrict__ out, int t, int T)
{
    int b = blockIdx.x;
    int tid = threadIdx.x;
    const float* lg = g_logits + (size_t)b * V_;
    float* op = out + ((size_t)b * T + t) * V_;
    int lane = tid & 31, w = tid >> 5;

    float bm = -1e30f; int bi = 0;
    for (int v = tid; v < V_; v += 512) {
        float x = lg[v];
        if (x > bm) { bm = x; bi = v; }
    }
    __shared__ float smax[16]; __shared__ int sidx[16]; __shared__ float ssum[16];
#pragma unroll
    for (int o = 16; o; o >>= 1) {
        float om = __shfl_xor_sync(0xffffffffu, bm, o);
        int   oi = __shfl_xor_sync(0xffffffffu, bi, o);
        if (om > bm || (om == bm && oi < bi)) { bm = om; bi = oi; }
    }
    if (!lane) { smax[w] = bm; sidx[w] = bi; }
    __syncthreads();
    if (tid == 0) {
        float M = smax[0]; int I = sidx[0];
        for (int i = 1; i < 16; i++)
            if (smax[i] > M || (smax[i] == M && sidx[i] < I)) { M = smax[i]; I = sidx[i]; }
        smax[0] = M;
        g_tok[b] = I;
    }
    __syncthreads();
    float mx = smax[0];

    float s = 0.f;
    for (int v = tid; v < V_; v += 512) s += __expf(lg[v] - mx);
#pragma unroll
    for (int o = 16; o; o >>= 1) s += __shfl_xor_sync(0xffffffffu, s, o);
    if (!lane) ssum[w] = s;
    __syncthreads();
    if (tid == 0) {
        float tt = 0.f;
        for (int i = 0; i < 16; i++) tt += ssum[i];
        ssum[0] = tt;
    }
    __syncthreads();
    float inv = __fdividef(1.f, ssum[0]);
    for (int v = tid; v < V_; v += 512) op[v] = __expf(lg[v] - mx) * inv;
}

// ---------------- launch ----------------
extern "C" void kernel_launch(void* const* d_in, const int* in_sizes, int n_in,
                              void* d_out, int out_size)
{
    const float* enc   = (const float*)d_in[0];
    const float* h0    = (const float*)d_in[1];
    const float* emb   = (const float*)d_in[2];
    const float* Wq    = (const float*)d_in[3];
    const float* Wk    = (const float*)d_in[4];
    const float* v_att = (const float*)d_in[5];
    const float* W_ih  = (const float*)d_in[6];
    const float* W_hh  = (const float*)d_in[7];
    const float* b_ih  = (const float*)d_in[8];
    const float* b_hh  = (const float*)d_in[9];
    const float* W1    = (const float*)d_in[10];
    const float* b1    = (const float*)d_in[11];
    const float* W2    = (const float*)d_in[12];
    const float* b2    = (const float*)d_in[13];
    float* out = (float*)d_out;
    const int T = out_size / (B_ * V_);

    float *p_keys, *p_rnn, *p_mlp, *p_h, *p_partA, *p_partB, *p_WihT, *p_WhhT;
    cudaGetSymbolAddress((void**)&p_keys,   g_keys);
    cudaGetSymbolAddress((void**)&p_rnn,    g_rnn_in);
    cudaGetSymbolAddress((void**)&p_mlp,    g_mlp_in);
    cudaGetSymbolAddress((void**)&p_h,      g_h);
    cudaGetSymbolAddress((void**)&p_partA,  g_partA);
    cudaGetSymbolAddress((void**)&p_partB,  g_partB);
    cudaGetSymbolAddress((void**)&p_WihT,   g_WihT);
    cudaGetSymbolAddress((void**)&p_WhhT,   g_WhhT);

    cudaFuncSetAttribute(logits_fused, cudaFuncAttributeMaxDynamicSharedMemorySize,
                         LG2_SMEM);

    // per-replay prep
    init_state<<<(B_ * H_ + 255) / 256, 256>>>(h0);
    transpose_k<<<dim3((E_ + K_) / 32, G3H / 32), dim3(32, 8)>>>(W_ih, p_WihT, G3H, E_ + K_);
    transpose_k<<<dim3(H_ / 32, G3H / 32), dim3(32, 8)>>>(W_hh, p_WhhT, G3H, H_);
    conv_w2<<<dim3(V_ / 32, 8), 256>>>(W2);
    gemm64<<<dim3(A_ / 128, (S_ * B_) / 64, 1), 256>>>(enc, Wk, p_keys, nullptr, K_, A_, 0);

    for (int t = 0; t < T; t++) {
        // qW = h @ Wq (split-K x16 -> partA)
        gemm64<<<dim3(A_ / 128, 1, 16), 256>>>(p_h, Wq, p_partA, nullptr, H_, A_, 0);
        attn_fused<<<B_, 512>>>(emb, v_att, enc);

        // gi = rnn_in @ W_ih^T (K=1024) AND gh = h @ W_hh^T (K=512), one launch
        gemm64_dual<<<dim3(G3H / 128, 2, 16), 256>>>(
            p_rnn, p_WihT, p_partA, E_ + K_,
            p_h,   p_WhhT, p_partB, H_, G3H);
        gru_fused<<<B_ * H_ / 256, 256>>>(b_ih, b_hh);

        // hidden = tanh(mlp_in @ W1 + b1) -> fp16 hi/lo (split-K x32)
        gemm64<<<dim3(H_ / 128, 1, 32), 256>>>(p_mlp, W1, p_partA, nullptr, E_ + H_ + K_, H_, 0);
        reduce_h16<<<B_ * H_ / 256, 256>>>(p_partA, b1);

        // logits (hh + lh/1024 + hl/1024 + b2), single wave
        logits_fused<<<125, 256, LG2_SMEM>>>(b2);

        softmax_v<<<B_, 512>>>(out, t, T);
    }
}